// round 1
// baseline (speedup 1.0000x reference)
#include <cuda_runtime.h>
#include <cuda_bf16.h>

// GPT_78932908966066 — fp32 baseline, Round 1.
// L=2, H=16, D=1024, HD=64, FF=4096, V=32000, S=1024, B=4.
// Output: logits [4096,32000] then h [4096,1024], float32.

#define NTOK   4096        // B*S
#define DMODEL 1024
#define NHEAD  16
#define HDIM   64
#define FFDIM  4096
#define VOCAB  32000
#define SEQ    1024
#define NLAYER 2

// ---------------- scratch (static device memory; no allocs) ----------------
__device__ float g_h  [NTOK * DMODEL];
__device__ float g_q  [NTOK * DMODEL];
__device__ float g_k  [NTOK * DMODEL];
__device__ float g_v  [NTOK * DMODEL];
__device__ float g_o  [NTOK * DMODEL];
__device__ float g_tmp[NTOK * DMODEL];
__device__ float g_f1 [NTOK * FFDIM];
__device__ float g_sc [67108864];   // 64 * 1024 * 1024 scores (256 MB)
__device__ int   g_is64;

// ---------------- int32/int64 token-id width detection ----------------
// If x is int64 (little-endian), every odd 32-bit word is 0 (values < 32000).
// If x is int32, the odd-indexed tokens are random in [0,32000) -> OR != 0.
__global__ void detect64_kernel(const int* __restrict__ x32) {
    __shared__ int red[256];
    int o = 0;
    for (int i = threadIdx.x; i < 2048; i += 256) o |= x32[2 * i + 1];
    red[threadIdx.x] = o;
    __syncthreads();
    for (int st = 128; st > 0; st >>= 1) {
        if (threadIdx.x < st) red[threadIdx.x] |= red[threadIdx.x + st];
        __syncthreads();
    }
    if (threadIdx.x == 0) g_is64 = (red[0] == 0) ? 1 : 0;
}

// ---------------- embedding ----------------
__global__ __launch_bounds__(256) void embed_kernel(
    const int* __restrict__ x32,
    const float* __restrict__ tok,
    const float* __restrict__ pos,
    float* __restrict__ h)
{
    int t = blockIdx.x;                 // token index 0..4095
    long long id;
    if (g_is64) id = ((const long long*)x32)[t];
    else        id = (long long)x32[t];
    int s = t & (SEQ - 1);
    const float* tr = tok + id * DMODEL;
    const float* pr = pos + (long long)s * DMODEL;
    float* hr = h + (long long)t * DMODEL;
    for (int i = threadIdx.x; i < DMODEL; i += 256)
        hr[i] = tr[i] + pr[i];
}

// ---------------- generic batched SGEMM (NN) ----------------
// C[m,n] = alpha * sum_k A[m,k]*B[k,n]  (+ bias[n])
// batch index z decomposed: zo = z / bdiv, zi = z % bdiv; ptr += zo*O + zi*I.
// Requires M,N multiples of 64 and K multiple of 16 (all shapes here comply).
__global__ __launch_bounds__(256) void sgemm_nn(
    int M, int N, int K,
    const float* __restrict__ A, long long aO, long long aI, int lda,
    const float* __restrict__ Bm, long long bO, long long bI, int ldb,
    float* __restrict__ C, long long cO, long long cI, int ldc,
    const float* __restrict__ bias, long long biasO, long long biasI,
    float alpha, int bdiv)
{
    int z = blockIdx.z;
    int zo = z / bdiv, zi = z - zo * bdiv;
    A  += zo * aO + zi * aI;
    Bm += zo * bO + zi * bI;
    C  += zo * cO + zi * cI;
    if (bias) bias += zo * biasO + zi * biasI;

    __shared__ __align__(16) float As[16][68];
    __shared__ __align__(16) float Bs[16][68];

    int tid = threadIdx.x;
    int tx = tid & 15, ty = tid >> 4;
    int rowBase = blockIdx.y * 64, colBase = blockIdx.x * 64;

    float acc[4][4] = {};

    for (int k0 = 0; k0 < K; k0 += 16) {
        #pragma unroll
        for (int i = 0; i < 4; i++) {
            int idx = tid + i * 256;
            int r = idx >> 4, kk = idx & 15;
            As[kk][r] = A[(long long)(rowBase + r) * lda + (k0 + kk)];
        }
        #pragma unroll
        for (int i = 0; i < 4; i++) {
            int idx = tid + i * 256;
            int kk = idx >> 6, c = idx & 63;
            Bs[kk][c] = Bm[(long long)(k0 + kk) * ldb + (colBase + c)];
        }
        __syncthreads();
        #pragma unroll
        for (int kk = 0; kk < 16; kk++) {
            float4 a4 = *(const float4*)&As[kk][ty * 4];
            float4 b4 = *(const float4*)&Bs[kk][tx * 4];
            float av[4] = {a4.x, a4.y, a4.z, a4.w};
            float bv[4] = {b4.x, b4.y, b4.z, b4.w};
            #pragma unroll
            for (int i = 0; i < 4; i++)
                #pragma unroll
                for (int j = 0; j < 4; j++)
                    acc[i][j] += av[i] * bv[j];
        }
        __syncthreads();
    }

    #pragma unroll
    for (int i = 0; i < 4; i++) {
        long long row = rowBase + ty * 4 + i;
        #pragma unroll
        for (int j = 0; j < 4; j++) {
            int col = colBase + tx * 4 + j;
            float v = alpha * acc[i][j];
            if (bias) v += bias[col];
            C[row * ldc + col] = v;
        }
    }
}

// ---------------- generic batched SGEMM (NT): C = alpha * A @ B^T ----------------
// C[m,n] = alpha * sum_k A[m,k]*B[n,k]
__global__ __launch_bounds__(256) void sgemm_nt(
    int M, int N, int K,
    const float* __restrict__ A, long long aO, long long aI, int lda,
    const float* __restrict__ Bm, long long bO, long long bI, int ldb,
    float* __restrict__ C, long long cO, long long cI, int ldc,
    float alpha, int bdiv)
{
    int z = blockIdx.z;
    int zo = z / bdiv, zi = z - zo * bdiv;
    A  += zo * aO + zi * aI;
    Bm += zo * bO + zi * bI;
    C  += zo * cO + zi * cI;

    __shared__ __align__(16) float As[16][68];
    __shared__ __align__(16) float Bs[16][68];

    int tid = threadIdx.x;
    int tx = tid & 15, ty = tid >> 4;
    int rowBase = blockIdx.y * 64, colBase = blockIdx.x * 64;

    float acc[4][4] = {};

    for (int k0 = 0; k0 < K; k0 += 16) {
        #pragma unroll
        for (int i = 0; i < 4; i++) {
            int idx = tid + i * 256;
            int r = idx >> 4, kk = idx & 15;
            As[kk][r] = A[(long long)(rowBase + r) * lda + (k0 + kk)];
        }
        #pragma unroll
        for (int i = 0; i < 4; i++) {
            int idx = tid + i * 256;
            int c = idx >> 4, kk = idx & 15;
            Bs[kk][c] = Bm[(long long)(colBase + c) * ldb + (k0 + kk)];
        }
        __syncthreads();
        #pragma unroll
        for (int kk = 0; kk < 16; kk++) {
            float4 a4 = *(const float4*)&As[kk][ty * 4];
            float4 b4 = *(const float4*)&Bs[kk][tx * 4];
            float av[4] = {a4.x, a4.y, a4.z, a4.w};
            float bv[4] = {b4.x, b4.y, b4.z, b4.w};
            #pragma unroll
            for (int i = 0; i < 4; i++)
                #pragma unroll
                for (int j = 0; j < 4; j++)
                    acc[i][j] += av[i] * bv[j];
        }
        __syncthreads();
    }

    #pragma unroll
    for (int i = 0; i < 4; i++) {
        long long row = rowBase + ty * 4 + i;
        #pragma unroll
        for (int j = 0; j < 4; j++) {
            int col = colBase + tx * 4 + j;
            C[row * ldc + col] = alpha * acc[i][j];
        }
    }
}

// ---------------- causal softmax over rows of the score matrix ----------------
// One block per row. Row r (global over 64 batches * 1024 rows): q = r % 1024,
// valid columns [0, q]; masked columns written as 0 so att@V over full K works.
__global__ __launch_bounds__(256) void softmax_causal(float* __restrict__ sc)
{
    __shared__ float red[256];
    long long row = blockIdx.x;
    int q = (int)(row & (SEQ - 1));
    int valid = q + 1;
    float* p = sc + row * SEQ;
    int tid = threadIdx.x;

    float m = -1e30f;
    for (int i = tid; i < valid; i += 256) m = fmaxf(m, p[i]);
    red[tid] = m; __syncthreads();
    for (int st = 128; st > 0; st >>= 1) {
        if (tid < st) red[tid] = fmaxf(red[tid], red[tid + st]);
        __syncthreads();
    }
    m = red[0];
    __syncthreads();

    float s = 0.f;
    for (int i = tid; i < valid; i += 256) {
        float e = __expf(p[i] - m);
        p[i] = e;
        s += e;
    }
    red[tid] = s; __syncthreads();
    for (int st = 128; st > 0; st >>= 1) {
        if (tid < st) red[tid] += red[tid + st];
        __syncthreads();
    }
    float inv = 1.f / red[0];

    for (int i = tid; i < valid; i += 256) p[i] *= inv;
    for (int i = valid + tid; i < SEQ; i += 256) p[i] = 0.f;
}

// ---------------- fused residual add + LayerNorm (in-place on h) ----------------
__global__ __launch_bounds__(256) void add_ln(
    float* __restrict__ h, const float* __restrict__ t,
    const float* __restrict__ w, const float* __restrict__ b)
{
    __shared__ float buf[DMODEL];
    __shared__ float red[256];
    long long base = (long long)blockIdx.x * DMODEL;
    int tid = threadIdx.x;

    float s = 0.f;
    for (int i = tid; i < DMODEL; i += 256) {
        float x = h[base + i] + t[base + i];
        buf[i] = x;
        s += x;
    }
    red[tid] = s; __syncthreads();
    for (int st = 128; st > 0; st >>= 1) {
        if (tid < st) red[tid] += red[tid + st];
        __syncthreads();
    }
    float mean = red[0] * (1.f / DMODEL);
    __syncthreads();

    float s2 = 0.f;
    for (int i = tid; i < DMODEL; i += 256) {
        float d = buf[i] - mean;
        s2 += d * d;
    }
    red[tid] = s2; __syncthreads();
    for (int st = 128; st > 0; st >>= 1) {
        if (tid < st) red[tid] += red[tid + st];
        __syncthreads();
    }
    float inv = rsqrtf(red[0] * (1.f / DMODEL) + 1e-5f);

    for (int i = tid; i < DMODEL; i += 256)
        h[base + i] = (buf[i] - mean) * inv * w[i] + b[i];
}

// ---------------- exact GELU, in place ----------------
__global__ __launch_bounds__(256) void gelu_kernel(float* __restrict__ p)
{
    long long i = ((long long)blockIdx.x * 256 + threadIdx.x) * 4;
    float4 v = *(float4*)(p + i);
    v.x = 0.5f * v.x * (1.f + erff(v.x * 0.70710678118654752f));
    v.y = 0.5f * v.y * (1.f + erff(v.y * 0.70710678118654752f));
    v.z = 0.5f * v.z * (1.f + erff(v.z * 0.70710678118654752f));
    v.w = 0.5f * v.w * (1.f + erff(v.w * 0.70710678118654752f));
    *(float4*)(p + i) = v;
}

// ---------------- copy h into tail of output ----------------
__global__ __launch_bounds__(256) void copy_kernel(float* __restrict__ dst,
                                                   const float* __restrict__ src)
{
    long long i = ((long long)blockIdx.x * 256 + threadIdx.x) * 4;
    *(float4*)(dst + i) = *(const float4*)(src + i);
}

// ---------------- launch ----------------
extern "C" void kernel_launch(void* const* d_in, const int* in_sizes, int n_in,
                              void* d_out, int out_size)
{
    const int*   x32     = (const int*)  d_in[0];   // int32 or int64 tokens
    const float* tok_emb = (const float*)d_in[1];
    const float* pos_emb = (const float*)d_in[2];
    const float* Wq      = (const float*)d_in[3];
    const float* bq      = (const float*)d_in[4];
    const float* Wk      = (const float*)d_in[5];
    const float* bk      = (const float*)d_in[6];
    const float* Wv      = (const float*)d_in[7];
    const float* bv      = (const float*)d_in[8];
    const float* Wo      = (const float*)d_in[9];
    const float* bo      = (const float*)d_in[10];
    const float* ln1w    = (const float*)d_in[11];
    const float* ln1b    = (const float*)d_in[12];
    const float* ln2w    = (const float*)d_in[13];
    const float* ln2b    = (const float*)d_in[14];
    const float* W1      = (const float*)d_in[15];
    const float* b1      = (const float*)d_in[16];
    const float* W2      = (const float*)d_in[17];
    const float* b2      = (const float*)d_in[18];
    const float* Wout    = (const float*)d_in[19];
    const float* bout    = (const float*)d_in[20];
    float* out = (float*)d_out;

    float *h, *q, *k, *v, *o, *tmp, *f1, *sc;
    cudaGetSymbolAddress((void**)&h,   g_h);
    cudaGetSymbolAddress((void**)&q,   g_q);
    cudaGetSymbolAddress((void**)&k,   g_k);
    cudaGetSymbolAddress((void**)&v,   g_v);
    cudaGetSymbolAddress((void**)&o,   g_o);
    cudaGetSymbolAddress((void**)&tmp, g_tmp);
    cudaGetSymbolAddress((void**)&f1,  g_f1);
    cudaGetSymbolAddress((void**)&sc,  g_sc);

    detect64_kernel<<<1, 256>>>(x32);
    embed_kernel<<<NTOK, 256>>>(x32, tok_emb, pos_emb, h);

    const long long WQKV_L = (long long)NHEAD * DMODEL * HDIM;  // 1048576
    const long long BQKV_L = (long long)NHEAD * HDIM;           // 1024
    const long long WO_L   = (long long)DMODEL * DMODEL;        // 1048576
    const long long W1_L   = (long long)DMODEL * FFDIM;         // 4194304
    const long long W2_L   = (long long)FFDIM * DMODEL;         // 4194304

    for (int l = 0; l < NLAYER; l++) {
        const float* Wq_l = Wq + l * WQKV_L;  const float* bq_l = bq + l * BQKV_L;
        const float* Wk_l = Wk + l * WQKV_L;  const float* bk_l = bk + l * BQKV_L;
        const float* Wv_l = Wv + l * WQKV_L;  const float* bv_l = bv + l * BQKV_L;
        const float* Wo_l = Wo + l * WO_L;    const float* bo_l = bo + l * DMODEL;
        const float* W1_l = W1 + l * W1_L;    const float* b1_l = b1 + l * FFDIM;
        const float* W2_l = W2 + l * W2_L;    const float* b2_l = b2 + l * DMODEL;

        // Q, K, V: batched over 16 heads. B_head = W[l][head] row-major [D, HD].
        // Output layout [tok, head*64 + e] (ldc = 1024, per-head column offset 64).
        sgemm_nn<<<dim3(1, 64, 16), 256>>>(NTOK, HDIM, DMODEL,
            h, 0, 0, DMODEL,
            Wq_l, (long long)DMODEL * HDIM, 0, HDIM,
            q, HDIM, 0, DMODEL,
            bq_l, HDIM, 0, 1.f, 1);
        sgemm_nn<<<dim3(1, 64, 16), 256>>>(NTOK, HDIM, DMODEL,
            h, 0, 0, DMODEL,
            Wk_l, (long long)DMODEL * HDIM, 0, HDIM,
            k, HDIM, 0, DMODEL,
            bk_l, HDIM, 0, 1.f, 1);
        sgemm_nn<<<dim3(1, 64, 16), 256>>>(NTOK, HDIM, DMODEL,
            h, 0, 0, DMODEL,
            Wv_l, (long long)DMODEL * HDIM, 0, HDIM,
            v, HDIM, 0, DMODEL,
            bv_l, HDIM, 0, 1.f, 1);

        // scores[z] = (1/8) * q_sub @ k_sub^T, z = b*16 + head (64 batches)
        sgemm_nt<<<dim3(16, 16, 64), 256>>>(SEQ, SEQ, HDIM,
            q, (long long)SEQ * DMODEL, HDIM, DMODEL,
            k, (long long)SEQ * DMODEL, HDIM, DMODEL,
            sc, 16LL * SEQ * SEQ, (long long)SEQ * SEQ, SEQ,
            0.125f, 16);

        // causal softmax: 64 * 1024 rows
        softmax_causal<<<64 * SEQ, 256>>>(sc);

        // o_sub = att @ v_sub  -> written into [tok, head*64+e] layout
        sgemm_nn<<<dim3(1, 16, 64), 256>>>(SEQ, HDIM, SEQ,
            sc, 16LL * SEQ * SEQ, (long long)SEQ * SEQ, SEQ,
            v, (long long)SEQ * DMODEL, HDIM, DMODEL,
            o, (long long)SEQ * DMODEL, HDIM, DMODEL,
            (const float*)nullptr, 0, 0, 1.f, 16);

        // attention output projection
        sgemm_nn<<<dim3(16, 64, 1), 256>>>(NTOK, DMODEL, DMODEL,
            o, 0, 0, DMODEL,
            Wo_l, 0, 0, DMODEL,
            tmp, 0, 0, DMODEL,
            bo_l, 0, 0, 1.f, 1);

        add_ln<<<NTOK, 256>>>(h, tmp, ln1w + l * DMODEL, ln1b + l * DMODEL);

        // FFN
        sgemm_nn<<<dim3(64, 64, 1), 256>>>(NTOK, FFDIM, DMODEL,
            h, 0, 0, DMODEL,
            W1_l, 0, 0, FFDIM,
            f1, 0, 0, FFDIM,
            b1_l, 0, 0, 1.f, 1);

        gelu_kernel<<<(NTOK * FFDIM) / 1024, 256>>>(f1);

        sgemm_nn<<<dim3(16, 64, 1), 256>>>(NTOK, DMODEL, FFDIM,
            f1, 0, 0, FFDIM,
            W2_l, 0, 0, DMODEL,
            tmp, 0, 0, DMODEL,
            b2_l, 0, 0, 1.f, 1);

        add_ln<<<NTOK, 256>>>(h, tmp, ln2w + l * DMODEL, ln2b + l * DMODEL);
    }

    // logits = h @ Wout + bout -> first 4096*32000 floats of output
    sgemm_nn<<<dim3(VOCAB / 64, NTOK / 64, 1), 256>>>(NTOK, VOCAB, DMODEL,
        h, 0, 0, DMODEL,
        Wout, 0, 0, VOCAB,
        out, 0, 0, VOCAB,
        bout, 0, 0, 1.f, 1);

    // final h -> tail of output
    copy_kernel<<<(NTOK * DMODEL) / 1024, 256>>>(out + (long long)NTOK * VOCAB, h);
}

// round 3
// speedup vs baseline: 1.9721x; 1.9721x over previous
#include <cuda_runtime.h>
#include <cuda_bf16.h>
#include <cstdint>

// GPT_78932908966066 — Round 3: mma.sync tf32 (sm_80-class HMMA; harness targets
// plain sm_103, so tcgen05/'103a' features are unavailable).
// L=2, H=16, D=1024, HD=64, FF=4096, V=32000, S=1024, B=4.

#define NTOK   4096
#define DMODEL 1024
#define NHEAD  16
#define HDIM   64
#define FFDIM  4096
#define VOCAB  32000
#define SEQ    1024
#define NLAYER 2

// ---------------- static scratch ----------------
__device__ float g_h   [NTOK * DMODEL];
__device__ float g_q   [NTOK * DMODEL];
__device__ float g_k   [NTOK * DMODEL];
__device__ float g_vt  [DMODEL * NTOK];      // v transposed [hd_global][tok]
__device__ float g_o   [NTOK * DMODEL];
__device__ float g_tmp [NTOK * DMODEL];
__device__ float g_f1  [NTOK * FFDIM];
__device__ float g_sc  [67108864];           // 64 * 1024 * 1024 scores
__device__ float g_wtq [DMODEL * DMODEL];
__device__ float g_wtk [DMODEL * DMODEL];
__device__ float g_wtv [DMODEL * DMODEL];
__device__ float g_wto [DMODEL * DMODEL];
__device__ float g_wt1 [FFDIM * DMODEL];
__device__ float g_wt2 [DMODEL * FFDIM];
__device__ float g_wtout[(size_t)VOCAB * DMODEL];
__device__ int   g_is64;

// ---------------- helpers ----------------
__device__ __forceinline__ uint32_t smem_u32(const void* p) {
    uint32_t a;
    asm("{ .reg .u64 t; cvta.to.shared.u64 t, %1; cvt.u32.u64 %0, t; }" : "=r"(a) : "l"(p));
    return a;
}
__device__ __forceinline__ void cpasync16(uint32_t dst, const float* src) {
    asm volatile("cp.async.cg.shared.global [%0], [%1], 16;" :: "r"(dst), "l"(src) : "memory");
}
__device__ __forceinline__ void cp_commit() {
    asm volatile("cp.async.commit_group;" ::: "memory");
}
__device__ __forceinline__ void cp_wait2() {
    asm volatile("cp.async.wait_group 2;" ::: "memory");
}
__device__ __forceinline__ uint32_t f2tf(float f) {
    uint32_t u;
    asm("cvt.rna.tf32.f32 %0, %1;" : "=r"(u) : "f"(f));
    return u;
}
__device__ __forceinline__ void mma_tf32(float* c, const uint32_t* a, const uint32_t* b) {
    asm volatile(
        "mma.sync.aligned.m16n8k8.row.col.f32.tf32.tf32.f32 "
        "{%0,%1,%2,%3}, {%4,%5,%6,%7}, {%8,%9}, {%0,%1,%2,%3};"
        : "+f"(c[0]), "+f"(c[1]), "+f"(c[2]), "+f"(c[3])
        : "r"(a[0]), "r"(a[1]), "r"(a[2]), "r"(a[3]), "r"(b[0]), "r"(b[1]));
}

// ---------------- tf32 mma.sync NT GEMM ----------------
// C[m,n] = alpha * sum_k A[m,k]*B[n,k] (+ bias). A:[M,K] rows, B:[N,K] rows.
// Block tile 128 x BN, K-stage 32, 3-stage cp.async pipeline, 256 threads.
// Warp grid 2(M) x 4(N): warp tile 64 x (BN/4). Row stride in smem = 36 floats.
template<int BN>
__global__ void __launch_bounds__(256, 1) gemm_mma(
    const float* __restrict__ A, long long aO, long long aI, int lda,
    const float* __restrict__ B, long long bO, long long bI, int ldb,
    float* __restrict__ C, long long cO, long long cI, int ldc,
    const float* __restrict__ bias, long long biasO, long long biasI, int biasRow,
    int K, float alpha, int bdiv, int causal)
{
    constexpr int WN  = BN / 4;     // warp N extent
    constexpr int NT_ = WN / 8;     // n-tiles per warp (8 wide each)
    constexpr int ASZ = 128 * 36;   // words per A stage
    constexpr int BSZ = BN  * 36;   // words per B stage

    extern __shared__ float sm[];
    const int rowBase = blockIdx.y * 128;
    const int colBase = blockIdx.x * BN;
    if (causal && colBase > rowBase + 127) return;

    const int z = blockIdx.z;
    const int zo = z / bdiv, zi = z - zo * bdiv;
    A += zo * aO + zi * aI + (long long)rowBase * lda;
    B += zo * bO + zi * bI + (long long)colBase * ldb;
    C += zo * cO + zi * cI;
    if (bias) bias += zo * biasO + zi * biasI;

    const int tid = threadIdx.x;
    const int wid = tid >> 5, lane = tid & 31;
    const int gid = lane >> 2, tig = lane & 3;
    const int warpM = wid & 1, warpN = wid >> 1;

    float* smB = sm + 3 * ASZ;
    const uint32_t smA_u = smem_u32(sm);
    const uint32_t smB_u = smem_u32(smB);

    const int nk = K >> 5;

    auto load_stage = [&](int s, int i) {
        const int k0 = i << 5;
        uint32_t ab = smA_u + (uint32_t)s * (ASZ * 4);
        #pragma unroll
        for (int c = 0; c < 4; c++) {                // 1024 A chunks / 256 thr
            int idx = tid + c * 256;
            int row = idx >> 3, part = idx & 7;
            cpasync16(ab + row * 144 + part * 16, A + (long long)row * lda + k0 + part * 4);
        }
        uint32_t bb = smB_u + (uint32_t)s * (BSZ * 4);
        #pragma unroll
        for (int c = 0; c < BN / 32; c++) {          // BN*8 chunks / 256 thr
            int idx = tid + c * 256;
            int row = idx >> 3, part = idx & 7;
            cpasync16(bb + row * 144 + part * 16, B + (long long)row * ldb + k0 + part * 4);
        }
    };

    float acc[4][NT_][4];
    #pragma unroll
    for (int mt = 0; mt < 4; mt++)
        #pragma unroll
        for (int nt = 0; nt < NT_; nt++)
            #pragma unroll
            for (int r = 0; r < 4; r++) acc[mt][nt][r] = 0.f;

    // prologue
    load_stage(0, 0); cp_commit();
    if (nk > 1) load_stage(1, 1);
    cp_commit();

    for (int i = 0; i < nk; i++) {
        if (i + 2 < nk) load_stage((i + 2) % 3, i + 2);
        cp_commit();
        cp_wait2();
        __syncthreads();

        const float* as = sm  + (i % 3) * ASZ;
        const float* bs = smB + (i % 3) * BSZ;
        #pragma unroll
        for (int kk = 0; kk < 32; kk += 8) {
            uint32_t af[4][4], bf[NT_][2];
            #pragma unroll
            for (int mt = 0; mt < 4; mt++) {
                const float* ap = as + (warpM * 64 + mt * 16 + gid) * 36 + kk + tig;
                af[mt][0] = f2tf(ap[0]);
                af[mt][1] = f2tf(ap[8 * 36]);
                af[mt][2] = f2tf(ap[4]);
                af[mt][3] = f2tf(ap[8 * 36 + 4]);
            }
            #pragma unroll
            for (int nt = 0; nt < NT_; nt++) {
                const float* bp = bs + (warpN * WN + nt * 8 + gid) * 36 + kk + tig;
                bf[nt][0] = f2tf(bp[0]);
                bf[nt][1] = f2tf(bp[4]);
            }
            #pragma unroll
            for (int mt = 0; mt < 4; mt++)
                #pragma unroll
                for (int nt = 0; nt < NT_; nt++)
                    mma_tf32(acc[mt][nt], af[mt], bf[nt]);
        }
        __syncthreads();
    }

    // epilogue: direct register -> gmem (float2 per fragment row)
    #pragma unroll
    for (int mt = 0; mt < 4; mt++) {
        #pragma unroll
        for (int nt = 0; nt < NT_; nt++) {
            int row0 = rowBase + warpM * 64 + mt * 16 + gid;
            int col0 = colBase + warpN * WN + nt * 8 + tig * 2;
            float b0 = 0.f, b1 = 0.f;
            if (bias && !biasRow) { b0 = bias[col0]; b1 = bias[col0 + 1]; }
            {
                float rb = (bias && biasRow) ? bias[row0] : 0.f;
                float2 v = make_float2(alpha * acc[mt][nt][0] + b0 + rb,
                                       alpha * acc[mt][nt][1] + b1 + rb);
                *(float2*)(C + (long long)row0 * ldc + col0) = v;
            }
            {
                float rb = (bias && biasRow) ? bias[row0 + 8] : 0.f;
                float2 v = make_float2(alpha * acc[mt][nt][2] + b0 + rb,
                                       alpha * acc[mt][nt][3] + b1 + rb);
                *(float2*)(C + (long long)(row0 + 8) * ldc + col0) = v;
            }
        }
    }
}

// ---------------- transpose ----------------
__global__ void __launch_bounds__(256) transpose_k(
    float* __restrict__ dst, const float* __restrict__ src,
    int R, int Cc, long long srcBatch, long long dstBatch)
{
    __shared__ float t[32][33];
    src += (long long)blockIdx.z * srcBatch;
    dst += (long long)blockIdx.z * dstBatch;
    int c0 = blockIdx.x * 32, r0 = blockIdx.y * 32;
    int x = threadIdx.x, y = threadIdx.y;
    #pragma unroll
    for (int j = 0; j < 32; j += 8)
        t[y + j][x] = src[(long long)(r0 + y + j) * Cc + c0 + x];
    __syncthreads();
    #pragma unroll
    for (int j = 0; j < 32; j += 8)
        dst[(long long)(c0 + y + j) * R + r0 + x] = t[x][y + j];
}

// ---------------- token width detect ----------------
__global__ void detect64_kernel(const int* __restrict__ x32) {
    __shared__ int red[256];
    int o = 0;
    for (int i = threadIdx.x; i < 2048; i += 256) o |= x32[2 * i + 1];
    red[threadIdx.x] = o; __syncthreads();
    for (int st = 128; st > 0; st >>= 1) {
        if (threadIdx.x < st) red[threadIdx.x] |= red[threadIdx.x + st];
        __syncthreads();
    }
    if (threadIdx.x == 0) g_is64 = (red[0] == 0) ? 1 : 0;
}

// ---------------- embedding ----------------
__global__ __launch_bounds__(256) void embed_kernel(
    const int* __restrict__ x32, const float* __restrict__ tok,
    const float* __restrict__ pos, float* __restrict__ h)
{
    int t = blockIdx.x;
    long long id = g_is64 ? ((const long long*)x32)[t] : (long long)x32[t];
    int s = t & (SEQ - 1);
    const float* tr = tok + id * DMODEL;
    const float* pr = pos + (long long)s * DMODEL;
    float* hr = h + (long long)t * DMODEL;
    for (int i = threadIdx.x; i < DMODEL; i += 256) hr[i] = tr[i] + pr[i];
}

// ---------------- causal softmax ----------------
__global__ __launch_bounds__(256) void softmax_causal(float* __restrict__ sc)
{
    __shared__ float red[256];
    long long row = blockIdx.x;
    int q = (int)(row & (SEQ - 1));
    int valid = q + 1;
    float* p = sc + row * SEQ;
    int tid = threadIdx.x;

    float m = -1e30f;
    for (int i = tid; i < valid; i += 256) m = fmaxf(m, p[i]);
    red[tid] = m; __syncthreads();
    for (int st = 128; st > 0; st >>= 1) {
        if (tid < st) red[tid] = fmaxf(red[tid], red[tid + st]);
        __syncthreads();
    }
    m = red[0]; __syncthreads();

    float s = 0.f;
    for (int i = tid; i < valid; i += 256) { float e = __expf(p[i] - m); p[i] = e; s += e; }
    red[tid] = s; __syncthreads();
    for (int st = 128; st > 0; st >>= 1) {
        if (tid < st) red[tid] += red[tid + st];
        __syncthreads();
    }
    float inv = 1.f / red[0];
    for (int i = tid; i < valid; i += 256) p[i] *= inv;
    for (int i = valid + tid; i < SEQ; i += 256) p[i] = 0.f;
}

// ---------------- residual + LayerNorm ----------------
__global__ __launch_bounds__(256) void add_ln(
    float* __restrict__ h, const float* __restrict__ t,
    const float* __restrict__ w, const float* __restrict__ b)
{
    __shared__ float buf[DMODEL];
    __shared__ float red[256];
    long long base = (long long)blockIdx.x * DMODEL;
    int tid = threadIdx.x;

    float s = 0.f;
    for (int i = tid; i < DMODEL; i += 256) {
        float x = h[base + i] + t[base + i];
        buf[i] = x; s += x;
    }
    red[tid] = s; __syncthreads();
    for (int st = 128; st > 0; st >>= 1) {
        if (tid < st) red[tid] += red[tid + st];
        __syncthreads();
    }
    float mean = red[0] * (1.f / DMODEL); __syncthreads();

    float s2 = 0.f;
    for (int i = tid; i < DMODEL; i += 256) { float d = buf[i] - mean; s2 += d * d; }
    red[tid] = s2; __syncthreads();
    for (int st = 128; st > 0; st >>= 1) {
        if (tid < st) red[tid] += red[tid + st];
        __syncthreads();
    }
    float inv = rsqrtf(red[0] * (1.f / DMODEL) + 1e-5f);
    for (int i = tid; i < DMODEL; i += 256)
        h[base + i] = (buf[i] - mean) * inv * w[i] + b[i];
}

// ---------------- exact GELU ----------------
__global__ __launch_bounds__(256) void gelu_kernel(float* __restrict__ p)
{
    long long i = ((long long)blockIdx.x * 256 + threadIdx.x) * 4;
    float4 v = *(float4*)(p + i);
    v.x = 0.5f * v.x * (1.f + erff(v.x * 0.70710678118654752f));
    v.y = 0.5f * v.y * (1.f + erff(v.y * 0.70710678118654752f));
    v.z = 0.5f * v.z * (1.f + erff(v.z * 0.70710678118654752f));
    v.w = 0.5f * v.w * (1.f + erff(v.w * 0.70710678118654752f));
    *(float4*)(p + i) = v;
}

__global__ __launch_bounds__(256) void copy_kernel(float* __restrict__ dst,
                                                   const float* __restrict__ src)
{
    long long i = ((long long)blockIdx.x * 256 + threadIdx.x) * 4;
    *(float4*)(dst + i) = *(const float4*)(src + i);
}

// ---------------- host side ----------------
static void gemm(const float* A, long long aO, long long aI, int lda,
                 const float* B, long long bO, long long bI, int ldb,
                 float* C, long long cO, long long cI, int ldc,
                 const float* bias, long long biasO, long long biasI, int biasRow,
                 int M, int N, int K, int Nt, float alpha, int bdiv, int batches, int causal)
{
    dim3 g(N / Nt, M / 128, batches);
    if (Nt == 128) {
        size_t sm = 3 * (128 * 36 + 128 * 36) * sizeof(float);   // 110592
        gemm_mma<128><<<g, 256, sm>>>(A, aO, aI, lda, B, bO, bI, ldb, C, cO, cI, ldc,
                                      bias, biasO, biasI, biasRow, K, alpha, bdiv, causal);
    } else {
        size_t sm = 3 * (128 * 36 + 64 * 36) * sizeof(float);    // 82944
        gemm_mma<64><<<g, 256, sm>>>(A, aO, aI, lda, B, bO, bI, ldb, C, cO, cI, ldc,
                                     bias, biasO, biasI, biasRow, K, alpha, bdiv, causal);
    }
}

extern "C" void kernel_launch(void* const* d_in, const int* in_sizes, int n_in,
                              void* d_out, int out_size)
{
    const int*   x32     = (const int*)  d_in[0];
    const float* tok_emb = (const float*)d_in[1];
    const float* pos_emb = (const float*)d_in[2];
    const float* Wq      = (const float*)d_in[3];
    const float* bq      = (const float*)d_in[4];
    const float* Wk      = (const float*)d_in[5];
    const float* bk      = (const float*)d_in[6];
    const float* Wv      = (const float*)d_in[7];
    const float* bv      = (const float*)d_in[8];
    const float* Wo      = (const float*)d_in[9];
    const float* bo      = (const float*)d_in[10];
    const float* ln1w    = (const float*)d_in[11];
    const float* ln1b    = (const float*)d_in[12];
    const float* ln2w    = (const float*)d_in[13];
    const float* ln2b    = (const float*)d_in[14];
    const float* W1      = (const float*)d_in[15];
    const float* b1      = (const float*)d_in[16];
    const float* W2      = (const float*)d_in[17];
    const float* b2      = (const float*)d_in[18];
    const float* Wout    = (const float*)d_in[19];
    const float* bout    = (const float*)d_in[20];
    float* out = (float*)d_out;

    float *h, *q, *k, *vt, *o, *tmp, *f1, *sc;
    float *wtq, *wtk, *wtv, *wto, *wt1, *wt2, *wtout;
    cudaGetSymbolAddress((void**)&h,    g_h);
    cudaGetSymbolAddress((void**)&q,    g_q);
    cudaGetSymbolAddress((void**)&k,    g_k);
    cudaGetSymbolAddress((void**)&vt,   g_vt);
    cudaGetSymbolAddress((void**)&o,    g_o);
    cudaGetSymbolAddress((void**)&tmp,  g_tmp);
    cudaGetSymbolAddress((void**)&f1,   g_f1);
    cudaGetSymbolAddress((void**)&sc,   g_sc);
    cudaGetSymbolAddress((void**)&wtq,  g_wtq);
    cudaGetSymbolAddress((void**)&wtk,  g_wtk);
    cudaGetSymbolAddress((void**)&wtv,  g_wtv);
    cudaGetSymbolAddress((void**)&wto,  g_wto);
    cudaGetSymbolAddress((void**)&wt1,  g_wt1);
    cudaGetSymbolAddress((void**)&wt2,  g_wt2);
    cudaGetSymbolAddress((void**)&wtout, g_wtout);

    cudaFuncSetAttribute(gemm_mma<128>, cudaFuncAttributeMaxDynamicSharedMemorySize, 110592);
    cudaFuncSetAttribute(gemm_mma<64>,  cudaFuncAttributeMaxDynamicSharedMemorySize, 82944);

    detect64_kernel<<<1, 256>>>(x32);
    embed_kernel<<<NTOK, 256>>>(x32, tok_emb, pos_emb, h);

    transpose_k<<<dim3(VOCAB / 32, DMODEL / 32, 1), dim3(32, 8)>>>(
        wtout, Wout, DMODEL, VOCAB, 0, 0);

    const long long WQKV_L = (long long)NHEAD * DMODEL * HDIM;
    const long long BQKV_L = (long long)NHEAD * HDIM;
    const long long WO_L   = (long long)DMODEL * DMODEL;
    const long long W1_L   = (long long)DMODEL * FFDIM;
    const long long W2_L   = (long long)FFDIM * DMODEL;

    for (int l = 0; l < NLAYER; l++) {
        const float* bq_l = bq + l * BQKV_L;
        const float* bk_l = bk + l * BQKV_L;
        const float* bv_l = bv + l * BQKV_L;
        const float* bo_l = bo + l * DMODEL;
        const float* b1_l = b1 + l * FFDIM;
        const float* b2_l = b2 + l * DMODEL;

        transpose_k<<<dim3(2, 32, 16), dim3(32, 8)>>>(wtq, Wq + l * WQKV_L,
            DMODEL, HDIM, (long long)DMODEL * HDIM, (long long)HDIM * DMODEL);
        transpose_k<<<dim3(2, 32, 16), dim3(32, 8)>>>(wtk, Wk + l * WQKV_L,
            DMODEL, HDIM, (long long)DMODEL * HDIM, (long long)HDIM * DMODEL);
        transpose_k<<<dim3(2, 32, 16), dim3(32, 8)>>>(wtv, Wv + l * WQKV_L,
            DMODEL, HDIM, (long long)DMODEL * HDIM, (long long)HDIM * DMODEL);
        transpose_k<<<dim3(32, 32, 1), dim3(32, 8)>>>(wto, Wo + l * WO_L,
            DMODEL, DMODEL, 0, 0);
        transpose_k<<<dim3(FFDIM / 32, DMODEL / 32, 1), dim3(32, 8)>>>(wt1, W1 + l * W1_L,
            DMODEL, FFDIM, 0, 0);
        transpose_k<<<dim3(DMODEL / 32, FFDIM / 32, 1), dim3(32, 8)>>>(wt2, W2 + l * W2_L,
            FFDIM, DMODEL, 0, 0);

        // q = h @ Wq + bq
        gemm(h, 0, 0, DMODEL, wtq, 0, 0, DMODEL, q, 0, 0, DMODEL,
             bq_l, 0, 0, 0, NTOK, DMODEL, DMODEL, 128, 1.f, 1, 1, 0);
        // k = h @ Wk + bk
        gemm(h, 0, 0, DMODEL, wtk, 0, 0, DMODEL, k, 0, 0, DMODEL,
             bk_l, 0, 0, 0, NTOK, DMODEL, DMODEL, 128, 1.f, 1, 1, 0);
        // v_t[hd][tok] = WvT @ h^T (+ bv per row)
        gemm(wtv, 0, 0, DMODEL, h, 0, 0, DMODEL, vt, 0, 0, NTOK,
             bv_l, 0, 0, 1, DMODEL, NTOK, DMODEL, 128, 1.f, 1, 1, 0);

        // scores = (1/8) q_sub @ k_sub^T, causal tile-skip (z = b*16 + head)
        gemm(q, (long long)SEQ * DMODEL, HDIM, DMODEL,
             k, (long long)SEQ * DMODEL, HDIM, DMODEL,
             sc, 16LL * SEQ * SEQ, (long long)SEQ * SEQ, SEQ,
             nullptr, 0, 0, 0, SEQ, SEQ, HDIM, 128, 0.125f, NHEAD, 64, 1);

        softmax_causal<<<64 * SEQ, 256>>>(sc);

        // o = att @ v  (B rows = vt rows)
        gemm(sc, 16LL * SEQ * SEQ, (long long)SEQ * SEQ, SEQ,
             vt, SEQ, (long long)HDIM * NTOK, NTOK,
             o, (long long)SEQ * DMODEL, HDIM, DMODEL,
             nullptr, 0, 0, 0, SEQ, HDIM, SEQ, 64, 1.f, NHEAD, 64, 0);

        // attn projection
        gemm(o, 0, 0, DMODEL, wto, 0, 0, DMODEL, tmp, 0, 0, DMODEL,
             bo_l, 0, 0, 0, NTOK, DMODEL, DMODEL, 128, 1.f, 1, 1, 0);

        add_ln<<<NTOK, 256>>>(h, tmp, ln1w + l * DMODEL, ln1b + l * DMODEL);

        // FFN
        gemm(h, 0, 0, DMODEL, wt1, 0, 0, DMODEL, f1, 0, 0, FFDIM,
             b1_l, 0, 0, 0, NTOK, FFDIM, DMODEL, 128, 1.f, 1, 1, 0);
        gelu_kernel<<<(NTOK * FFDIM) / 1024, 256>>>(f1);
        gemm(f1, 0, 0, FFDIM, wt2, 0, 0, FFDIM, tmp, 0, 0, DMODEL,
             b2_l, 0, 0, 0, NTOK, DMODEL, FFDIM, 128, 1.f, 1, 1, 0);

        add_ln<<<NTOK, 256>>>(h, tmp, ln2w + l * DMODEL, ln2b + l * DMODEL);
    }

    // logits
    gemm(h, 0, 0, DMODEL, wtout, 0, 0, DMODEL, out, 0, 0, VOCAB,
         bout, 0, 0, 0, NTOK, VOCAB, DMODEL, 128, 1.f, 1, 1, 0);

    copy_kernel<<<(NTOK * DMODEL) / 1024, 256>>>(out + (long long)NTOK * VOCAB, h);
}

// round 4
// speedup vs baseline: 3.8171x; 1.9355x over previous
#include <cuda_runtime.h>
#include <cuda_bf16.h>
#include <cstdint>

// GPT_78932908966066 — Round 4: 64x64 warp tiles + fused flash attention + fused GELU.
// L=2, H=16, D=1024, HD=64, FF=4096, V=32000, S=1024, B=4.

#define NTOK   4096
#define DMODEL 1024
#define NHEAD  16
#define HDIM   64
#define FFDIM  4096
#define VOCAB  32000
#define SEQ    1024
#define NLAYER 2

// ---------------- static scratch ----------------
__device__ float g_h   [NTOK * DMODEL];
__device__ float g_q   [NTOK * DMODEL];
__device__ float g_k   [NTOK * DMODEL];
__device__ float g_vt  [DMODEL * NTOK];      // v transposed [hd_global][tok]
__device__ float g_o   [NTOK * DMODEL];
__device__ float g_tmp [NTOK * DMODEL];
__device__ float g_f1  [NTOK * FFDIM];
__device__ float g_wtq [DMODEL * DMODEL];
__device__ float g_wtk [DMODEL * DMODEL];
__device__ float g_wtv [DMODEL * DMODEL];
__device__ float g_wto [DMODEL * DMODEL];
__device__ float g_wt1 [FFDIM * DMODEL];
__device__ float g_wt2 [DMODEL * FFDIM];
__device__ float g_wtout[(size_t)VOCAB * DMODEL];
__device__ int   g_is64;

// ---------------- helpers ----------------
__device__ __forceinline__ uint32_t smem_u32(const void* p) {
    uint32_t a;
    asm("{ .reg .u64 t; cvta.to.shared.u64 t, %1; cvt.u32.u64 %0, t; }" : "=r"(a) : "l"(p));
    return a;
}
__device__ __forceinline__ void cpasync16(uint32_t dst, const float* src) {
    asm volatile("cp.async.cg.shared.global [%0], [%1], 16;" :: "r"(dst), "l"(src) : "memory");
}
__device__ __forceinline__ void cp_commit() {
    asm volatile("cp.async.commit_group;" ::: "memory");
}
__device__ __forceinline__ uint32_t f2tf(float f) {
    uint32_t u;
    asm("cvt.rna.tf32.f32 %0, %1;" : "=r"(u) : "f"(f));
    return u;
}
__device__ __forceinline__ void mma_tf32(float* c, const uint32_t* a, const uint32_t* b) {
    asm volatile(
        "mma.sync.aligned.m16n8k8.row.col.f32.tf32.tf32.f32 "
        "{%0,%1,%2,%3}, {%4,%5,%6,%7}, {%8,%9}, {%0,%1,%2,%3};"
        : "+f"(c[0]), "+f"(c[1]), "+f"(c[2]), "+f"(c[3])
        : "r"(a[0]), "r"(a[1]), "r"(a[2]), "r"(a[3]), "r"(b[0]), "r"(b[1]));
}

// ---------------- tf32 mma.sync NT GEMM, 128x128 tile, 4 warps (64x64 each) ----
// C[m,n] = alpha * sum_k A[m,k]*B[n,k] (+ bias, opt GELU). A:[M,K], B:[N,K] rows.
__global__ void __launch_bounds__(128, 1) gemm_mma(
    const float* __restrict__ A, long long aO, long long aI, int lda,
    const float* __restrict__ B, long long bO, long long bI, int ldb,
    float* __restrict__ C, long long cO, long long cI, int ldc,
    const float* __restrict__ bias, long long biasO, long long biasI, int biasRow,
    int K, float alpha, int bdiv, int gelu)
{
    constexpr int ASZ = 128 * 36;
    constexpr int BSZ = 128 * 36;

    extern __shared__ float sm[];
    const int rowBase = blockIdx.y * 128;
    const int colBase = blockIdx.x * 128;

    const int z = blockIdx.z;
    const int zo = z / bdiv, zi = z - zo * bdiv;
    A += zo * aO + zi * aI + (long long)rowBase * lda;
    B += zo * bO + zi * bI + (long long)colBase * ldb;
    C += zo * cO + zi * cI;
    if (bias) bias += zo * biasO + zi * biasI;

    const int tid = threadIdx.x;
    const int wid = tid >> 5, lane = tid & 31;
    const int gid = lane >> 2, tig = lane & 3;
    const int warpM = wid & 1, warpN = wid >> 1;

    float* smB = sm + 3 * ASZ;
    const uint32_t smA_u = smem_u32(sm);
    const uint32_t smB_u = smem_u32(smB);

    const int nk = K >> 5;

    auto load_stage = [&](int s, int i) {
        const int k0 = i << 5;
        uint32_t ab = smA_u + (uint32_t)s * (ASZ * 4);
        #pragma unroll
        for (int c = 0; c < 8; c++) {
            int idx = tid + c * 128;
            int row = idx >> 3, part = idx & 7;
            cpasync16(ab + row * 144 + part * 16, A + (long long)row * lda + k0 + part * 4);
        }
        uint32_t bb = smB_u + (uint32_t)s * (BSZ * 4);
        #pragma unroll
        for (int c = 0; c < 8; c++) {
            int idx = tid + c * 128;
            int row = idx >> 3, part = idx & 7;
            cpasync16(bb + row * 144 + part * 16, B + (long long)row * ldb + k0 + part * 4);
        }
    };

    float acc[4][8][4];
    #pragma unroll
    for (int mt = 0; mt < 4; mt++)
        #pragma unroll
        for (int nt = 0; nt < 8; nt++)
            #pragma unroll
            for (int r = 0; r < 4; r++) acc[mt][nt][r] = 0.f;

    load_stage(0, 0); cp_commit();
    if (nk > 1) load_stage(1, 1);
    cp_commit();

    for (int i = 0; i < nk; i++) {
        if (i + 2 < nk) load_stage((i + 2) % 3, i + 2);
        cp_commit();
        asm volatile("cp.async.wait_group 2;" ::: "memory");
        __syncthreads();

        const float* as = sm  + (i % 3) * ASZ;
        const float* bs = smB + (i % 3) * BSZ;
        #pragma unroll
        for (int kk = 0; kk < 32; kk += 8) {
            uint32_t af[4][4], bf[8][2];
            #pragma unroll
            for (int mt = 0; mt < 4; mt++) {
                const float* ap = as + (warpM * 64 + mt * 16 + gid) * 36 + kk + tig;
                af[mt][0] = f2tf(ap[0]);
                af[mt][1] = f2tf(ap[8 * 36]);
                af[mt][2] = f2tf(ap[4]);
                af[mt][3] = f2tf(ap[8 * 36 + 4]);
            }
            #pragma unroll
            for (int nt = 0; nt < 8; nt++) {
                const float* bp = bs + (warpN * 64 + nt * 8 + gid) * 36 + kk + tig;
                bf[nt][0] = f2tf(bp[0]);
                bf[nt][1] = f2tf(bp[4]);
            }
            #pragma unroll
            for (int mt = 0; mt < 4; mt++)
                #pragma unroll
                for (int nt = 0; nt < 8; nt++)
                    mma_tf32(acc[mt][nt], af[mt], bf[nt]);
        }
        __syncthreads();
    }

    #pragma unroll
    for (int mt = 0; mt < 4; mt++) {
        #pragma unroll
        for (int nt = 0; nt < 8; nt++) {
            int row0 = rowBase + warpM * 64 + mt * 16 + gid;
            int col0 = colBase + warpN * 64 + nt * 8 + tig * 2;
            float b0 = 0.f, b1 = 0.f;
            if (bias && !biasRow) { b0 = bias[col0]; b1 = bias[col0 + 1]; }
            #pragma unroll
            for (int hh = 0; hh < 2; hh++) {
                int row = row0 + hh * 8;
                float rb = (bias && biasRow) ? bias[row] : 0.f;
                float v0 = alpha * acc[mt][nt][hh * 2 + 0] + b0 + rb;
                float v1 = alpha * acc[mt][nt][hh * 2 + 1] + b1 + rb;
                if (gelu) {
                    v0 = 0.5f * v0 * (1.f + erff(v0 * 0.70710678118654752f));
                    v1 = 0.5f * v1 * (1.f + erff(v1 * 0.70710678118654752f));
                }
                *(float2*)(C + (long long)row * ldc + col0) = make_float2(v0, v1);
            }
        }
    }
}

// ---------------- fused flash attention ----------------
// grid (8 q-tiles, 64 z=b*16+h), 256 threads (8 warps x 16 q-rows).
// q,k: [4096,1024] tok-major (head cols h*64..); vt: [1024,4096] hd-major.
// Writes o[tok, h*64+e] = softmax(q k^T / 8, causal) @ v.
__global__ void __launch_bounds__(256, 1) flash_attn(
    const float* __restrict__ q, const float* __restrict__ k,
    const float* __restrict__ vt, float* __restrict__ og)
{
    extern __shared__ float sm[];
    constexpr int KS0 = 0, KS1 = 8704, VS0 = 17408, VS1 = 25856, PS = 34304;

    const int qi = blockIdx.x;
    const int z  = blockIdx.y;
    const int b  = z >> 4, hh = z & 15;
    const int hcol = hh * 64;
    const int qtok0 = b * 1024 + qi * 128;

    const int tid = threadIdx.x;
    const int w = tid >> 5, lane = tid & 31;
    const int gid = lane >> 2, tig = lane & 3;

    const uint32_t sbase = smem_u32(sm);

    // Q fragments, scaled by 1/8, register resident
    uint32_t qf[8][4];
    {
        const float* qb = q + (long long)(qtok0 + w * 16) * 1024 + hcol;
        #pragma unroll
        for (int kk = 0; kk < 8; kk++) {
            qf[kk][0] = f2tf(0.125f * qb[gid * 1024 + kk * 8 + tig]);
            qf[kk][1] = f2tf(0.125f * qb[(gid + 8) * 1024 + kk * 8 + tig]);
            qf[kk][2] = f2tf(0.125f * qb[gid * 1024 + kk * 8 + tig + 4]);
            qf[kk][3] = f2tf(0.125f * qb[(gid + 8) * 1024 + kk * 8 + tig + 4]);
        }
    }

    float oa[8][4];
    #pragma unroll
    for (int nt = 0; nt < 8; nt++)
        #pragma unroll
        for (int r = 0; r < 4; r++) oa[nt][r] = 0.f;
    float m_l = -1e30f, m_h = -1e30f, l_l = 0.f, l_h = 0.f;

    auto load_kv = [&](int j, int buf) {
        const float* kb = k + (long long)(b * 1024 + j * 128) * 1024 + hcol;
        uint32_t kd = sbase + (buf ? KS1 : KS0) * 4;
        #pragma unroll
        for (int c = 0; c < 8; c++) {
            int idx = tid + c * 256;
            int row = idx >> 4, part = idx & 15;
            cpasync16(kd + row * 272 + part * 16, kb + (long long)row * 1024 + part * 4);
        }
        const float* vb = vt + (long long)hcol * 4096 + b * 1024 + j * 128;
        uint32_t vd = sbase + (buf ? VS1 : VS0) * 4;
        #pragma unroll
        for (int c = 0; c < 8; c++) {
            int idx = tid + c * 256;
            int row = idx >> 5, part = idx & 31;
            cpasync16(vd + row * 528 + part * 16, vb + (long long)row * 4096 + part * 4);
        }
    };

    load_kv(0, 0);
    cp_commit();

    for (int j = 0; j <= qi; j++) {
        const int buf = j & 1;
        __syncthreads();                     // all reads of buf^1 (iter j-1) done
        if (j < qi) load_kv(j + 1, buf ^ 1);
        cp_commit();
        asm volatile("cp.async.wait_group 1;" ::: "memory");
        __syncthreads();                     // tile j data visible to all

        const float* Ks = sm + (buf ? KS1 : KS0);
        const float* Vs = sm + (buf ? VS1 : VS0);
        float* Psm = sm + PS;

        // S = (Q/8) K^T : warp computes 16 x 128
        float sa[16][4];
        #pragma unroll
        for (int nt = 0; nt < 16; nt++)
            #pragma unroll
            for (int r = 0; r < 4; r++) sa[nt][r] = 0.f;
        #pragma unroll
        for (int kk = 0; kk < 8; kk++) {
            #pragma unroll
            for (int nt = 0; nt < 16; nt++) {
                const float* bp = Ks + (nt * 8 + gid) * 68 + kk * 8 + tig;
                uint32_t bf[2] = { f2tf(bp[0]), f2tf(bp[4]) };
                mma_tf32(sa[nt], qf[kk], bf);
            }
        }

        if (j == qi) {      // causal mask on diagonal tile
            int rl = w * 16 + gid, rh = rl + 8;
            #pragma unroll
            for (int nt = 0; nt < 16; nt++) {
                int c0 = nt * 8 + tig * 2, c1 = c0 + 1;
                if (c0 > rl) sa[nt][0] = -1e30f;
                if (c1 > rl) sa[nt][1] = -1e30f;
                if (c0 > rh) sa[nt][2] = -1e30f;
                if (c1 > rh) sa[nt][3] = -1e30f;
            }
        }

        // online softmax
        float mxl = -1e30f, mxh = -1e30f;
        #pragma unroll
        for (int nt = 0; nt < 16; nt++) {
            mxl = fmaxf(mxl, fmaxf(sa[nt][0], sa[nt][1]));
            mxh = fmaxf(mxh, fmaxf(sa[nt][2], sa[nt][3]));
        }
        mxl = fmaxf(mxl, __shfl_xor_sync(0xffffffffu, mxl, 1));
        mxl = fmaxf(mxl, __shfl_xor_sync(0xffffffffu, mxl, 2));
        mxh = fmaxf(mxh, __shfl_xor_sync(0xffffffffu, mxh, 1));
        mxh = fmaxf(mxh, __shfl_xor_sync(0xffffffffu, mxh, 2));
        float nml = fmaxf(m_l, mxl), nmh = fmaxf(m_h, mxh);
        float cl = __expf(m_l - nml), ch = __expf(m_h - nmh);
        m_l = nml; m_h = nmh;

        float sl = 0.f, sh = 0.f;
        #pragma unroll
        for (int nt = 0; nt < 16; nt++) {
            float p0 = __expf(sa[nt][0] - m_l);
            float p1 = __expf(sa[nt][1] - m_l);
            float p2 = __expf(sa[nt][2] - m_h);
            float p3 = __expf(sa[nt][3] - m_h);
            sl += p0 + p1; sh += p2 + p3;
            *(float2*)(Psm + (w * 16 + gid) * 132 + nt * 8 + tig * 2) = make_float2(p0, p1);
            *(float2*)(Psm + (w * 16 + gid + 8) * 132 + nt * 8 + tig * 2) = make_float2(p2, p3);
        }
        sl += __shfl_xor_sync(0xffffffffu, sl, 1);
        sl += __shfl_xor_sync(0xffffffffu, sl, 2);
        sh += __shfl_xor_sync(0xffffffffu, sh, 1);
        sh += __shfl_xor_sync(0xffffffffu, sh, 2);
        l_l = l_l * cl + sl;
        l_h = l_h * ch + sh;
        #pragma unroll
        for (int nt = 0; nt < 8; nt++) {
            oa[nt][0] *= cl; oa[nt][1] *= cl;
            oa[nt][2] *= ch; oa[nt][3] *= ch;
        }
        __syncwarp();    // P rows are warp-private: warp-level visibility suffices

        // O += P V^T  (A = P[16 x 128] smem, B = Vs[64 x 128] smem)
        #pragma unroll
        for (int kk = 0; kk < 16; kk++) {
            const float* pp = Psm + (w * 16 + gid) * 132 + kk * 8 + tig;
            uint32_t af[4] = { f2tf(pp[0]), f2tf(pp[8 * 132]),
                               f2tf(pp[4]), f2tf(pp[8 * 132 + 4]) };
            #pragma unroll
            for (int nt = 0; nt < 8; nt++) {
                const float* vp = Vs + (nt * 8 + gid) * 132 + kk * 8 + tig;
                uint32_t bf[2] = { f2tf(vp[0]), f2tf(vp[4]) };
                mma_tf32(oa[nt], af, bf);
            }
        }
    }

    float il = 1.f / l_l, ih = 1.f / l_h;
    #pragma unroll
    for (int nt = 0; nt < 8; nt++) {
        long long r0 = qtok0 + w * 16 + gid;
        int c0 = hcol + nt * 8 + tig * 2;
        *(float2*)(og + r0 * 1024 + c0) = make_float2(oa[nt][0] * il, oa[nt][1] * il);
        *(float2*)(og + (r0 + 8) * 1024 + c0) = make_float2(oa[nt][2] * ih, oa[nt][3] * ih);
    }
}

// ---------------- transpose ----------------
__global__ void __launch_bounds__(256) transpose_k(
    float* __restrict__ dst, const float* __restrict__ src,
    int R, int Cc, long long srcBatch, long long dstBatch)
{
    __shared__ float t[32][33];
    src += (long long)blockIdx.z * srcBatch;
    dst += (long long)blockIdx.z * dstBatch;
    int c0 = blockIdx.x * 32, r0 = blockIdx.y * 32;
    int x = threadIdx.x, y = threadIdx.y;
    #pragma unroll
    for (int j = 0; j < 32; j += 8)
        t[y + j][x] = src[(long long)(r0 + y + j) * Cc + c0 + x];
    __syncthreads();
    #pragma unroll
    for (int j = 0; j < 32; j += 8)
        dst[(long long)(c0 + y + j) * R + r0 + x] = t[x][y + j];
}

// ---------------- token width detect ----------------
__global__ void detect64_kernel(const int* __restrict__ x32) {
    __shared__ int red[256];
    int o = 0;
    for (int i = threadIdx.x; i < 2048; i += 256) o |= x32[2 * i + 1];
    red[threadIdx.x] = o; __syncthreads();
    for (int st = 128; st > 0; st >>= 1) {
        if (threadIdx.x < st) red[threadIdx.x] |= red[threadIdx.x + st];
        __syncthreads();
    }
    if (threadIdx.x == 0) g_is64 = (red[0] == 0) ? 1 : 0;
}

// ---------------- embedding ----------------
__global__ __launch_bounds__(256) void embed_kernel(
    const int* __restrict__ x32, const float* __restrict__ tok,
    const float* __restrict__ pos, float* __restrict__ h)
{
    int t = blockIdx.x;
    long long id = g_is64 ? ((const long long*)x32)[t] : (long long)x32[t];
    int s = t & (SEQ - 1);
    const float* tr = tok + id * DMODEL;
    const float* pr = pos + (long long)s * DMODEL;
    float* hr = h + (long long)t * DMODEL;
    for (int i = threadIdx.x; i < DMODEL; i += 256) hr[i] = tr[i] + pr[i];
}

// ---------------- residual + LayerNorm ----------------
__global__ __launch_bounds__(256) void add_ln(
    float* __restrict__ h, const float* __restrict__ t,
    const float* __restrict__ w, const float* __restrict__ b)
{
    __shared__ float buf[DMODEL];
    __shared__ float red[256];
    long long base = (long long)blockIdx.x * DMODEL;
    int tid = threadIdx.x;

    float s = 0.f;
    for (int i = tid; i < DMODEL; i += 256) {
        float x = h[base + i] + t[base + i];
        buf[i] = x; s += x;
    }
    red[tid] = s; __syncthreads();
    for (int st = 128; st > 0; st >>= 1) {
        if (tid < st) red[tid] += red[tid + st];
        __syncthreads();
    }
    float mean = red[0] * (1.f / DMODEL); __syncthreads();

    float s2 = 0.f;
    for (int i = tid; i < DMODEL; i += 256) { float d = buf[i] - mean; s2 += d * d; }
    red[tid] = s2; __syncthreads();
    for (int st = 128; st > 0; st >>= 1) {
        if (tid < st) red[tid] += red[tid + st];
        __syncthreads();
    }
    float inv = rsqrtf(red[0] * (1.f / DMODEL) + 1e-5f);
    for (int i = tid; i < DMODEL; i += 256)
        h[base + i] = (buf[i] - mean) * inv * w[i] + b[i];
}

__global__ __launch_bounds__(256) void copy_kernel(float* __restrict__ dst,
                                                   const float* __restrict__ src)
{
    long long i = ((long long)blockIdx.x * 256 + threadIdx.x) * 4;
    *(float4*)(dst + i) = *(const float4*)(src + i);
}

// ---------------- host side ----------------
static void gemm(const float* A, long long aO, long long aI, int lda,
                 const float* B, long long bO, long long bI, int ldb,
                 float* C, long long cO, long long cI, int ldc,
                 const float* bias, long long biasO, long long biasI, int biasRow,
                 int M, int N, int K, float alpha, int bdiv, int batches, int gelu)
{
    size_t smem = 3 * (128 * 36 + 128 * 36) * sizeof(float);  // 110592
    dim3 g(N / 128, M / 128, batches);
    gemm_mma<<<g, 128, smem>>>(A, aO, aI, lda, B, bO, bI, ldb, C, cO, cI, ldc,
                               bias, biasO, biasI, biasRow, K, alpha, bdiv, gelu);
}

extern "C" void kernel_launch(void* const* d_in, const int* in_sizes, int n_in,
                              void* d_out, int out_size)
{
    const int*   x32     = (const int*)  d_in[0];
    const float* tok_emb = (const float*)d_in[1];
    const float* pos_emb = (const float*)d_in[2];
    const float* Wq      = (const float*)d_in[3];
    const float* bq      = (const float*)d_in[4];
    const float* Wk      = (const float*)d_in[5];
    const float* bk      = (const float*)d_in[6];
    const float* Wv      = (const float*)d_in[7];
    const float* bv      = (const float*)d_in[8];
    const float* Wo      = (const float*)d_in[9];
    const float* bo      = (const float*)d_in[10];
    const float* ln1w    = (const float*)d_in[11];
    const float* ln1b    = (const float*)d_in[12];
    const float* ln2w    = (const float*)d_in[13];
    const float* ln2b    = (const float*)d_in[14];
    const float* W1      = (const float*)d_in[15];
    const float* b1      = (const float*)d_in[16];
    const float* W2      = (const float*)d_in[17];
    const float* b2      = (const float*)d_in[18];
    const float* Wout    = (const float*)d_in[19];
    const float* bout    = (const float*)d_in[20];
    float* out = (float*)d_out;

    float *h, *q, *k, *vt, *o, *tmp, *f1;
    float *wtq, *wtk, *wtv, *wto, *wt1, *wt2, *wtout;
    cudaGetSymbolAddress((void**)&h,    g_h);
    cudaGetSymbolAddress((void**)&q,    g_q);
    cudaGetSymbolAddress((void**)&k,    g_k);
    cudaGetSymbolAddress((void**)&vt,   g_vt);
    cudaGetSymbolAddress((void**)&o,    g_o);
    cudaGetSymbolAddress((void**)&tmp,  g_tmp);
    cudaGetSymbolAddress((void**)&f1,   g_f1);
    cudaGetSymbolAddress((void**)&wtq,  g_wtq);
    cudaGetSymbolAddress((void**)&wtk,  g_wtk);
    cudaGetSymbolAddress((void**)&wtv,  g_wtv);
    cudaGetSymbolAddress((void**)&wto,  g_wto);
    cudaGetSymbolAddress((void**)&wt1,  g_wt1);
    cudaGetSymbolAddress((void**)&wt2,  g_wt2);
    cudaGetSymbolAddress((void**)&wtout, g_wtout);

    cudaFuncSetAttribute(gemm_mma, cudaFuncAttributeMaxDynamicSharedMemorySize, 110592);
    cudaFuncSetAttribute(flash_attn, cudaFuncAttributeMaxDynamicSharedMemorySize, 204800);

    detect64_kernel<<<1, 256>>>(x32);
    embed_kernel<<<NTOK, 256>>>(x32, tok_emb, pos_emb, h);

    transpose_k<<<dim3(VOCAB / 32, DMODEL / 32, 1), dim3(32, 8)>>>(
        wtout, Wout, DMODEL, VOCAB, 0, 0);

    const long long WQKV_L = (long long)NHEAD * DMODEL * HDIM;
    const long long BQKV_L = (long long)NHEAD * HDIM;
    const long long WO_L   = (long long)DMODEL * DMODEL;
    const long long W1_L   = (long long)DMODEL * FFDIM;
    const long long W2_L   = (long long)FFDIM * DMODEL;

    for (int l = 0; l < NLAYER; l++) {
        const float* bq_l = bq + l * BQKV_L;
        const float* bk_l = bk + l * BQKV_L;
        const float* bv_l = bv + l * BQKV_L;
        const float* bo_l = bo + l * DMODEL;
        const float* b1_l = b1 + l * FFDIM;
        const float* b2_l = b2 + l * DMODEL;

        transpose_k<<<dim3(2, 32, 16), dim3(32, 8)>>>(wtq, Wq + l * WQKV_L,
            DMODEL, HDIM, (long long)DMODEL * HDIM, (long long)HDIM * DMODEL);
        transpose_k<<<dim3(2, 32, 16), dim3(32, 8)>>>(wtk, Wk + l * WQKV_L,
            DMODEL, HDIM, (long long)DMODEL * HDIM, (long long)HDIM * DMODEL);
        transpose_k<<<dim3(2, 32, 16), dim3(32, 8)>>>(wtv, Wv + l * WQKV_L,
            DMODEL, HDIM, (long long)DMODEL * HDIM, (long long)HDIM * DMODEL);
        transpose_k<<<dim3(32, 32, 1), dim3(32, 8)>>>(wto, Wo + l * WO_L,
            DMODEL, DMODEL, 0, 0);
        transpose_k<<<dim3(FFDIM / 32, DMODEL / 32, 1), dim3(32, 8)>>>(wt1, W1 + l * W1_L,
            DMODEL, FFDIM, 0, 0);
        transpose_k<<<dim3(DMODEL / 32, FFDIM / 32, 1), dim3(32, 8)>>>(wt2, W2 + l * W2_L,
            FFDIM, DMODEL, 0, 0);

        // q = h @ Wq + bq ; k = h @ Wk + bk
        gemm(h, 0, 0, DMODEL, wtq, 0, 0, DMODEL, q, 0, 0, DMODEL,
             bq_l, 0, 0, 0, NTOK, DMODEL, DMODEL, 1.f, 1, 1, 0);
        gemm(h, 0, 0, DMODEL, wtk, 0, 0, DMODEL, k, 0, 0, DMODEL,
             bk_l, 0, 0, 0, NTOK, DMODEL, DMODEL, 1.f, 1, 1, 0);
        // v_t[hd][tok] = WvT @ h^T (+ bv per row)
        gemm(wtv, 0, 0, DMODEL, h, 0, 0, DMODEL, vt, 0, 0, NTOK,
             bv_l, 0, 0, 1, DMODEL, NTOK, DMODEL, 1.f, 1, 1, 0);

        // fused attention -> o
        flash_attn<<<dim3(8, 64), 256, 204800>>>(q, k, vt, o);

        // attn projection
        gemm(o, 0, 0, DMODEL, wto, 0, 0, DMODEL, tmp, 0, 0, DMODEL,
             bo_l, 0, 0, 0, NTOK, DMODEL, DMODEL, 1.f, 1, 1, 0);

        add_ln<<<NTOK, 256>>>(h, tmp, ln1w + l * DMODEL, ln1b + l * DMODEL);

        // FFN (GELU fused into W1 epilogue)
        gemm(h, 0, 0, DMODEL, wt1, 0, 0, DMODEL, f1, 0, 0, FFDIM,
             b1_l, 0, 0, 0, NTOK, FFDIM, DMODEL, 1.f, 1, 1, 1);
        gemm(f1, 0, 0, FFDIM, wt2, 0, 0, FFDIM, tmp, 0, 0, DMODEL,
             b2_l, 0, 0, 0, NTOK, DMODEL, FFDIM, 1.f, 1, 1, 0);

        add_ln<<<NTOK, 256>>>(h, tmp, ln2w + l * DMODEL, ln2b + l * DMODEL);
    }

    // logits
    gemm(h, 0, 0, DMODEL, wtout, 0, 0, DMODEL, out, 0, 0, VOCAB,
         bout, 0, 0, 0, NTOK, VOCAB, DMODEL, 1.f, 1, 1, 0);

    copy_kernel<<<(NTOK * DMODEL) / 1024, 256>>>(out + (long long)NTOK * VOCAB, h);
}

// round 5
// speedup vs baseline: 3.8658x; 1.0128x over previous
#include <cuda_runtime.h>
#include <cuda_bf16.h>
#include <cstdint>

// GPT_78932908966066 — Round 5: 256x128 CTA tile (8 warps, 2/SMSP), cvt-flag
// templated tf32 GEMM, weights pre-rounded to tf32, fused flash attention.
// L=2, H=16, D=1024, HD=64, FF=4096, V=32000, S=1024, B=4.

#define NTOK   4096
#define DMODEL 1024
#define NHEAD  16
#define HDIM   64
#define FFDIM  4096
#define VOCAB  32000
#define SEQ    1024
#define NLAYER 2

// ---------------- static scratch ----------------
__device__ float g_h   [NTOK * DMODEL];
__device__ float g_q   [NTOK * DMODEL];
__device__ float g_k   [NTOK * DMODEL];
__device__ float g_vt  [DMODEL * NTOK];
__device__ float g_o   [NTOK * DMODEL];
__device__ float g_tmp [NTOK * DMODEL];
__device__ float g_f1  [NTOK * FFDIM];
__device__ float g_wtq [DMODEL * DMODEL];
__device__ float g_wtk [DMODEL * DMODEL];
__device__ float g_wtv [DMODEL * DMODEL];
__device__ float g_wto [DMODEL * DMODEL];
__device__ float g_wt1 [FFDIM * DMODEL];
__device__ float g_wt2 [DMODEL * FFDIM];
__device__ float g_wtout[(size_t)VOCAB * DMODEL];
__device__ int   g_is64;

// ---------------- helpers ----------------
__device__ __forceinline__ uint32_t smem_u32(const void* p) {
    uint32_t a;
    asm("{ .reg .u64 t; cvta.to.shared.u64 t, %1; cvt.u32.u64 %0, t; }" : "=r"(a) : "l"(p));
    return a;
}
__device__ __forceinline__ void cpasync16(uint32_t dst, const float* src) {
    asm volatile("cp.async.cg.shared.global [%0], [%1], 16;" :: "r"(dst), "l"(src) : "memory");
}
__device__ __forceinline__ void cp_commit() {
    asm volatile("cp.async.commit_group;" ::: "memory");
}
__device__ __forceinline__ uint32_t f2tf(float f) {
    uint32_t u;
    asm("cvt.rna.tf32.f32 %0, %1;" : "=r"(u) : "f"(f));
    return u;
}
__device__ __forceinline__ void mma_tf32(float* c, const uint32_t* a, const uint32_t* b) {
    asm volatile(
        "mma.sync.aligned.m16n8k8.row.col.f32.tf32.tf32.f32 "
        "{%0,%1,%2,%3}, {%4,%5,%6,%7}, {%8,%9}, {%0,%1,%2,%3};"
        : "+f"(c[0]), "+f"(c[1]), "+f"(c[2]), "+f"(c[3])
        : "r"(a[0]), "r"(a[1]), "r"(a[2]), "r"(a[3]), "r"(b[0]), "r"(b[1]));
}

// ---------------- tf32 NT GEMM: 256x128 CTA tile, 8 warps (64x64 each) ----------
// C[m,n] = alpha * sum_k A[m,k]*B[n,k] (+ bias, opt GELU).
// ACVT/BCVT: whether operand needs fp32->tf32 rounding (0 if pre-rounded).
template<int ACVT, int BCVT>
__global__ void __launch_bounds__(256, 1) gemm_mma(
    const float* __restrict__ A, long long aO, long long aI, int lda,
    const float* __restrict__ B, long long bO, long long bI, int ldb,
    float* __restrict__ C, long long cO, long long cI, int ldc,
    const float* __restrict__ bias, long long biasO, long long biasI, int biasRow,
    int K, float alpha, int bdiv, int gelu)
{
    constexpr int ASZ = 256 * 36;    // words per A stage
    constexpr int BSZ = 128 * 36;    // words per B stage

    extern __shared__ float sm[];
    const int rowBase = blockIdx.y * 256;
    const int colBase = blockIdx.x * 128;

    const int z = blockIdx.z;
    const int zo = z / bdiv, zi = z - zo * bdiv;
    A += zo * aO + zi * aI + (long long)rowBase * lda;
    B += zo * bO + zi * bI + (long long)colBase * ldb;
    C += zo * cO + zi * cI;
    if (bias) bias += zo * biasO + zi * biasI;

    const int tid = threadIdx.x;
    const int wid = tid >> 5, lane = tid & 31;
    const int gid = lane >> 2, tig = lane & 3;
    const int warpM = wid & 3, warpN = wid >> 2;

    float* smB = sm + 3 * ASZ;
    const uint32_t smA_u = smem_u32(sm);
    const uint32_t smB_u = smem_u32(smB);

    const int nk = K >> 5;

    auto load_stage = [&](int s, int i) {
        const int k0 = i << 5;
        uint32_t ab = smA_u + (uint32_t)s * (ASZ * 4);
        #pragma unroll
        for (int c = 0; c < 8; c++) {                 // 2048 A chunks / 256 thr
            int idx = tid + c * 256;
            int row = idx >> 3, part = idx & 7;
            cpasync16(ab + row * 144 + part * 16, A + (long long)row * lda + k0 + part * 4);
        }
        uint32_t bb = smB_u + (uint32_t)s * (BSZ * 4);
        #pragma unroll
        for (int c = 0; c < 4; c++) {                 // 1024 B chunks / 256 thr
            int idx = tid + c * 256;
            int row = idx >> 3, part = idx & 7;
            cpasync16(bb + row * 144 + part * 16, B + (long long)row * ldb + k0 + part * 4);
        }
    };

    float acc[4][8][4];
    #pragma unroll
    for (int mt = 0; mt < 4; mt++)
        #pragma unroll
        for (int nt = 0; nt < 8; nt++)
            #pragma unroll
            for (int r = 0; r < 4; r++) acc[mt][nt][r] = 0.f;

    load_stage(0, 0); cp_commit();
    if (nk > 1) load_stage(1, 1);
    cp_commit();

    for (int i = 0; i < nk; i++) {
        if (i + 2 < nk) load_stage((i + 2) % 3, i + 2);
        cp_commit();
        asm volatile("cp.async.wait_group 2;" ::: "memory");
        __syncthreads();

        const float* as = sm  + (i % 3) * ASZ;
        const float* bs = smB + (i % 3) * BSZ;
        #pragma unroll
        for (int kk = 0; kk < 32; kk += 8) {
            uint32_t af[4][4], bf[8][2];
            #pragma unroll
            for (int mt = 0; mt < 4; mt++) {
                const float* ap = as + (warpM * 64 + mt * 16 + gid) * 36 + kk + tig;
                if (ACVT) {
                    af[mt][0] = f2tf(ap[0]);
                    af[mt][1] = f2tf(ap[8 * 36]);
                    af[mt][2] = f2tf(ap[4]);
                    af[mt][3] = f2tf(ap[8 * 36 + 4]);
                } else {
                    af[mt][0] = __float_as_uint(ap[0]);
                    af[mt][1] = __float_as_uint(ap[8 * 36]);
                    af[mt][2] = __float_as_uint(ap[4]);
                    af[mt][3] = __float_as_uint(ap[8 * 36 + 4]);
                }
            }
            #pragma unroll
            for (int nt = 0; nt < 8; nt++) {
                const float* bp = bs + (warpN * 64 + nt * 8 + gid) * 36 + kk + tig;
                if (BCVT) {
                    bf[nt][0] = f2tf(bp[0]);
                    bf[nt][1] = f2tf(bp[4]);
                } else {
                    bf[nt][0] = __float_as_uint(bp[0]);
                    bf[nt][1] = __float_as_uint(bp[4]);
                }
            }
            #pragma unroll
            for (int mt = 0; mt < 4; mt++)
                #pragma unroll
                for (int nt = 0; nt < 8; nt++)
                    mma_tf32(acc[mt][nt], af[mt], bf[nt]);
        }
        __syncthreads();
    }

    #pragma unroll
    for (int mt = 0; mt < 4; mt++) {
        #pragma unroll
        for (int nt = 0; nt < 8; nt++) {
            int row0 = rowBase + warpM * 64 + mt * 16 + gid;
            int col0 = colBase + warpN * 64 + nt * 8 + tig * 2;
            float b0 = 0.f, b1 = 0.f;
            if (bias && !biasRow) { b0 = bias[col0]; b1 = bias[col0 + 1]; }
            #pragma unroll
            for (int hh = 0; hh < 2; hh++) {
                int row = row0 + hh * 8;
                float rb = (bias && biasRow) ? bias[row] : 0.f;
                float v0 = alpha * acc[mt][nt][hh * 2 + 0] + b0 + rb;
                float v1 = alpha * acc[mt][nt][hh * 2 + 1] + b1 + rb;
                if (gelu) {
                    v0 = 0.5f * v0 * (1.f + erff(v0 * 0.70710678118654752f));
                    v1 = 0.5f * v1 * (1.f + erff(v1 * 0.70710678118654752f));
                    v0 = __uint_as_float(f2tf(v0));   // pre-round for next GEMM
                    v1 = __uint_as_float(f2tf(v1));
                }
                *(float2*)(C + (long long)row * ldc + col0) = make_float2(v0, v1);
            }
        }
    }
}

// ---------------- fused flash attention (unchanged from R4) ----------------
__global__ void __launch_bounds__(256, 1) flash_attn(
    const float* __restrict__ q, const float* __restrict__ k,
    const float* __restrict__ vt, float* __restrict__ og)
{
    extern __shared__ float sm[];
    constexpr int KS0 = 0, KS1 = 8704, VS0 = 17408, VS1 = 25856, PS = 34304;

    const int qi = blockIdx.x;
    const int z  = blockIdx.y;
    const int b  = z >> 4, hh = z & 15;
    const int hcol = hh * 64;
    const int qtok0 = b * 1024 + qi * 128;

    const int tid = threadIdx.x;
    const int w = tid >> 5, lane = tid & 31;
    const int gid = lane >> 2, tig = lane & 3;

    const uint32_t sbase = smem_u32(sm);

    uint32_t qf[8][4];
    {
        const float* qb = q + (long long)(qtok0 + w * 16) * 1024 + hcol;
        #pragma unroll
        for (int kk = 0; kk < 8; kk++) {
            qf[kk][0] = f2tf(0.125f * qb[gid * 1024 + kk * 8 + tig]);
            qf[kk][1] = f2tf(0.125f * qb[(gid + 8) * 1024 + kk * 8 + tig]);
            qf[kk][2] = f2tf(0.125f * qb[gid * 1024 + kk * 8 + tig + 4]);
            qf[kk][3] = f2tf(0.125f * qb[(gid + 8) * 1024 + kk * 8 + tig + 4]);
        }
    }

    float oa[8][4];
    #pragma unroll
    for (int nt = 0; nt < 8; nt++)
        #pragma unroll
        for (int r = 0; r < 4; r++) oa[nt][r] = 0.f;
    float m_l = -1e30f, m_h = -1e30f, l_l = 0.f, l_h = 0.f;

    auto load_kv = [&](int j, int buf) {
        const float* kb = k + (long long)(b * 1024 + j * 128) * 1024 + hcol;
        uint32_t kd = sbase + (buf ? KS1 : KS0) * 4;
        #pragma unroll
        for (int c = 0; c < 8; c++) {
            int idx = tid + c * 256;
            int row = idx >> 4, part = idx & 15;
            cpasync16(kd + row * 272 + part * 16, kb + (long long)row * 1024 + part * 4);
        }
        const float* vb = vt + (long long)hcol * 4096 + b * 1024 + j * 128;
        uint32_t vd = sbase + (buf ? VS1 : VS0) * 4;
        #pragma unroll
        for (int c = 0; c < 8; c++) {
            int idx = tid + c * 256;
            int row = idx >> 5, part = idx & 31;
            cpasync16(vd + row * 528 + part * 16, vb + (long long)row * 4096 + part * 4);
        }
    };

    load_kv(0, 0);
    cp_commit();

    for (int j = 0; j <= qi; j++) {
        const int buf = j & 1;
        __syncthreads();
        if (j < qi) load_kv(j + 1, buf ^ 1);
        cp_commit();
        asm volatile("cp.async.wait_group 1;" ::: "memory");
        __syncthreads();

        const float* Ks = sm + (buf ? KS1 : KS0);
        const float* Vs = sm + (buf ? VS1 : VS0);
        float* Psm = sm + PS;

        float sa[16][4];
        #pragma unroll
        for (int nt = 0; nt < 16; nt++)
            #pragma unroll
            for (int r = 0; r < 4; r++) sa[nt][r] = 0.f;
        #pragma unroll
        for (int kk = 0; kk < 8; kk++) {
            #pragma unroll
            for (int nt = 0; nt < 16; nt++) {
                const float* bp = Ks + (nt * 8 + gid) * 68 + kk * 8 + tig;
                uint32_t bf[2] = { f2tf(bp[0]), f2tf(bp[4]) };
                mma_tf32(sa[nt], qf[kk], bf);
            }
        }

        if (j == qi) {
            int rl = w * 16 + gid, rh = rl + 8;
            #pragma unroll
            for (int nt = 0; nt < 16; nt++) {
                int c0 = nt * 8 + tig * 2, c1 = c0 + 1;
                if (c0 > rl) sa[nt][0] = -1e30f;
                if (c1 > rl) sa[nt][1] = -1e30f;
                if (c0 > rh) sa[nt][2] = -1e30f;
                if (c1 > rh) sa[nt][3] = -1e30f;
            }
        }

        float mxl = -1e30f, mxh = -1e30f;
        #pragma unroll
        for (int nt = 0; nt < 16; nt++) {
            mxl = fmaxf(mxl, fmaxf(sa[nt][0], sa[nt][1]));
            mxh = fmaxf(mxh, fmaxf(sa[nt][2], sa[nt][3]));
        }
        mxl = fmaxf(mxl, __shfl_xor_sync(0xffffffffu, mxl, 1));
        mxl = fmaxf(mxl, __shfl_xor_sync(0xffffffffu, mxl, 2));
        mxh = fmaxf(mxh, __shfl_xor_sync(0xffffffffu, mxh, 1));
        mxh = fmaxf(mxh, __shfl_xor_sync(0xffffffffu, mxh, 2));
        float nml = fmaxf(m_l, mxl), nmh = fmaxf(m_h, mxh);
        float cl = __expf(m_l - nml), ch = __expf(m_h - nmh);
        m_l = nml; m_h = nmh;

        float sl = 0.f, sh = 0.f;
        #pragma unroll
        for (int nt = 0; nt < 16; nt++) {
            float p0 = __expf(sa[nt][0] - m_l);
            float p1 = __expf(sa[nt][1] - m_l);
            float p2 = __expf(sa[nt][2] - m_h);
            float p3 = __expf(sa[nt][3] - m_h);
            sl += p0 + p1; sh += p2 + p3;
            *(float2*)(Psm + (w * 16 + gid) * 132 + nt * 8 + tig * 2) = make_float2(p0, p1);
            *(float2*)(Psm + (w * 16 + gid + 8) * 132 + nt * 8 + tig * 2) = make_float2(p2, p3);
        }
        sl += __shfl_xor_sync(0xffffffffu, sl, 1);
        sl += __shfl_xor_sync(0xffffffffu, sl, 2);
        sh += __shfl_xor_sync(0xffffffffu, sh, 1);
        sh += __shfl_xor_sync(0xffffffffu, sh, 2);
        l_l = l_l * cl + sl;
        l_h = l_h * ch + sh;
        #pragma unroll
        for (int nt = 0; nt < 8; nt++) {
            oa[nt][0] *= cl; oa[nt][1] *= cl;
            oa[nt][2] *= ch; oa[nt][3] *= ch;
        }
        __syncwarp();

        #pragma unroll
        for (int kk = 0; kk < 16; kk++) {
            const float* pp = Psm + (w * 16 + gid) * 132 + kk * 8 + tig;
            uint32_t af[4] = { f2tf(pp[0]), f2tf(pp[8 * 132]),
                               f2tf(pp[4]), f2tf(pp[8 * 132 + 4]) };
            #pragma unroll
            for (int nt = 0; nt < 8; nt++) {
                const float* vp = Vs + (nt * 8 + gid) * 132 + kk * 8 + tig;
                uint32_t bf[2] = { f2tf(vp[0]), f2tf(vp[4]) };
                mma_tf32(oa[nt], af, bf);
            }
        }
    }

    float il = 1.f / l_l, ih = 1.f / l_h;
    #pragma unroll
    for (int nt = 0; nt < 8; nt++) {
        long long r0 = qtok0 + w * 16 + gid;
        int c0 = hcol + nt * 8 + tig * 2;
        *(float2*)(og + r0 * 1024 + c0) = make_float2(oa[nt][0] * il, oa[nt][1] * il);
        *(float2*)(og + (r0 + 8) * 1024 + c0) = make_float2(oa[nt][2] * ih, oa[nt][3] * ih);
    }
}

// ---------------- transpose + pre-round to tf32 ----------------
__global__ void __launch_bounds__(256) transpose_k(
    float* __restrict__ dst, const float* __restrict__ src,
    int R, int Cc, long long srcBatch, long long dstBatch)
{
    __shared__ float t[32][33];
    src += (long long)blockIdx.z * srcBatch;
    dst += (long long)blockIdx.z * dstBatch;
    int c0 = blockIdx.x * 32, r0 = blockIdx.y * 32;
    int x = threadIdx.x, y = threadIdx.y;
    #pragma unroll
    for (int j = 0; j < 32; j += 8)
        t[y + j][x] = src[(long long)(r0 + y + j) * Cc + c0 + x];
    __syncthreads();
    #pragma unroll
    for (int j = 0; j < 32; j += 8)
        dst[(long long)(c0 + y + j) * R + r0 + x] = __uint_as_float(f2tf(t[x][y + j]));
}

// ---------------- token width detect ----------------
__global__ void detect64_kernel(const int* __restrict__ x32) {
    __shared__ int red[256];
    int o = 0;
    for (int i = threadIdx.x; i < 2048; i += 256) o |= x32[2 * i + 1];
    red[threadIdx.x] = o; __syncthreads();
    for (int st = 128; st > 0; st >>= 1) {
        if (threadIdx.x < st) red[threadIdx.x] |= red[threadIdx.x + st];
        __syncthreads();
    }
    if (threadIdx.x == 0) g_is64 = (red[0] == 0) ? 1 : 0;
}

// ---------------- embedding ----------------
__global__ __launch_bounds__(256) void embed_kernel(
    const int* __restrict__ x32, const float* __restrict__ tok,
    const float* __restrict__ pos, float* __restrict__ h)
{
    int t = blockIdx.x;
    long long id = g_is64 ? ((const long long*)x32)[t] : (long long)x32[t];
    int s = t & (SEQ - 1);
    const float* tr = tok + id * DMODEL;
    const float* pr = pos + (long long)s * DMODEL;
    float* hr = h + (long long)t * DMODEL;
    for (int i = threadIdx.x; i < DMODEL; i += 256) hr[i] = tr[i] + pr[i];
}

// ---------------- residual + LayerNorm ----------------
__global__ __launch_bounds__(256) void add_ln(
    float* __restrict__ h, const float* __restrict__ t,
    const float* __restrict__ w, const float* __restrict__ b)
{
    __shared__ float buf[DMODEL];
    __shared__ float red[256];
    long long base = (long long)blockIdx.x * DMODEL;
    int tid = threadIdx.x;

    float s = 0.f;
    for (int i = tid; i < DMODEL; i += 256) {
        float x = h[base + i] + t[base + i];
        buf[i] = x; s += x;
    }
    red[tid] = s; __syncthreads();
    for (int st = 128; st > 0; st >>= 1) {
        if (tid < st) red[tid] += red[tid + st];
        __syncthreads();
    }
    float mean = red[0] * (1.f / DMODEL); __syncthreads();

    float s2 = 0.f;
    for (int i = tid; i < DMODEL; i += 256) { float d = buf[i] - mean; s2 += d * d; }
    red[tid] = s2; __syncthreads();
    for (int st = 128; st > 0; st >>= 1) {
        if (tid < st) red[tid] += red[tid + st];
        __syncthreads();
    }
    float inv = rsqrtf(red[0] * (1.f / DMODEL) + 1e-5f);
    for (int i = tid; i < DMODEL; i += 256)
        h[base + i] = (buf[i] - mean) * inv * w[i] + b[i];
}

__global__ __launch_bounds__(256) void copy_kernel(float* __restrict__ dst,
                                                   const float* __restrict__ src)
{
    long long i = ((long long)blockIdx.x * 256 + threadIdx.x) * 4;
    *(float4*)(dst + i) = *(const float4*)(src + i);
}

// ---------------- host side ----------------
#define GEMM_SMEM (3 * (256 * 36 + 128 * 36) * 4)   // 165888

static void gemm(int acvt, int bcvt,
                 const float* A, long long aO, long long aI, int lda,
                 const float* B, long long bO, long long bI, int ldb,
                 float* C, long long cO, long long cI, int ldc,
                 const float* bias, long long biasO, long long biasI, int biasRow,
                 int M, int N, int K, float alpha, int bdiv, int batches, int gelu)
{
    dim3 g(N / 128, M / 256, batches);
    if (acvt && bcvt)
        gemm_mma<1,1><<<g, 256, GEMM_SMEM>>>(A, aO, aI, lda, B, bO, bI, ldb, C, cO, cI, ldc,
                                             bias, biasO, biasI, biasRow, K, alpha, bdiv, gelu);
    else if (acvt)
        gemm_mma<1,0><<<g, 256, GEMM_SMEM>>>(A, aO, aI, lda, B, bO, bI, ldb, C, cO, cI, ldc,
                                             bias, biasO, biasI, biasRow, K, alpha, bdiv, gelu);
    else if (bcvt)
        gemm_mma<0,1><<<g, 256, GEMM_SMEM>>>(A, aO, aI, lda, B, bO, bI, ldb, C, cO, cI, ldc,
                                             bias, biasO, biasI, biasRow, K, alpha, bdiv, gelu);
    else
        gemm_mma<0,0><<<g, 256, GEMM_SMEM>>>(A, aO, aI, lda, B, bO, bI, ldb, C, cO, cI, ldc,
                                             bias, biasO, biasI, biasRow, K, alpha, bdiv, gelu);
}

extern "C" void kernel_launch(void* const* d_in, const int* in_sizes, int n_in,
                              void* d_out, int out_size)
{
    const int*   x32     = (const int*)  d_in[0];
    const float* tok_emb = (const float*)d_in[1];
    const float* pos_emb = (const float*)d_in[2];
    const float* Wq      = (const float*)d_in[3];
    const float* bq      = (const float*)d_in[4];
    const float* Wk      = (const float*)d_in[5];
    const float* bk      = (const float*)d_in[6];
    const float* Wv      = (const float*)d_in[7];
    const float* bv      = (const float*)d_in[8];
    const float* Wo      = (const float*)d_in[9];
    const float* bo      = (const float*)d_in[10];
    const float* ln1w    = (const float*)d_in[11];
    const float* ln1b    = (const float*)d_in[12];
    const float* ln2w    = (const float*)d_in[13];
    const float* ln2b    = (const float*)d_in[14];
    const float* W1      = (const float*)d_in[15];
    const float* b1      = (const float*)d_in[16];
    const float* W2      = (const float*)d_in[17];
    const float* b2      = (const float*)d_in[18];
    const float* Wout    = (const float*)d_in[19];
    const float* bout    = (const float*)d_in[20];
    float* out = (float*)d_out;

    float *h, *q, *k, *vt, *o, *tmp, *f1;
    float *wtq, *wtk, *wtv, *wto, *wt1, *wt2, *wtout;
    cudaGetSymbolAddress((void**)&h,    g_h);
    cudaGetSymbolAddress((void**)&q,    g_q);
    cudaGetSymbolAddress((void**)&k,    g_k);
    cudaGetSymbolAddress((void**)&vt,   g_vt);
    cudaGetSymbolAddress((void**)&o,    g_o);
    cudaGetSymbolAddress((void**)&tmp,  g_tmp);
    cudaGetSymbolAddress((void**)&f1,   g_f1);
    cudaGetSymbolAddress((void**)&wtq,  g_wtq);
    cudaGetSymbolAddress((void**)&wtk,  g_wtk);
    cudaGetSymbolAddress((void**)&wtv,  g_wtv);
    cudaGetSymbolAddress((void**)&wto,  g_wto);
    cudaGetSymbolAddress((void**)&wt1,  g_wt1);
    cudaGetSymbolAddress((void**)&wt2,  g_wt2);
    cudaGetSymbolAddress((void**)&wtout, g_wtout);

    cudaFuncSetAttribute(gemm_mma<1,1>, cudaFuncAttributeMaxDynamicSharedMemorySize, GEMM_SMEM);
    cudaFuncSetAttribute(gemm_mma<1,0>, cudaFuncAttributeMaxDynamicSharedMemorySize, GEMM_SMEM);
    cudaFuncSetAttribute(gemm_mma<0,1>, cudaFuncAttributeMaxDynamicSharedMemorySize, GEMM_SMEM);
    cudaFuncSetAttribute(gemm_mma<0,0>, cudaFuncAttributeMaxDynamicSharedMemorySize, GEMM_SMEM);
    cudaFuncSetAttribute(flash_attn, cudaFuncAttributeMaxDynamicSharedMemorySize, 204800);

    detect64_kernel<<<1, 256>>>(x32);
    embed_kernel<<<NTOK, 256>>>(x32, tok_emb, pos_emb, h);

    transpose_k<<<dim3(VOCAB / 32, DMODEL / 32, 1), dim3(32, 8)>>>(
        wtout, Wout, DMODEL, VOCAB, 0, 0);

    const long long WQKV_L = (long long)NHEAD * DMODEL * HDIM;
    const long long BQKV_L = (long long)NHEAD * HDIM;
    const long long WO_L   = (long long)DMODEL * DMODEL;
    const long long W1_L   = (long long)DMODEL * FFDIM;
    const long long W2_L   = (long long)FFDIM * DMODEL;

    for (int l = 0; l < NLAYER; l++) {
        const float* bq_l = bq + l * BQKV_L;
        const float* bk_l = bk + l * BQKV_L;
        const float* bv_l = bv + l * BQKV_L;
        const float* bo_l = bo + l * DMODEL;
        const float* b1_l = b1 + l * FFDIM;
        const float* b2_l = b2 + l * DMODEL;

        transpose_k<<<dim3(2, 32, 16), dim3(32, 8)>>>(wtq, Wq + l * WQKV_L,
            DMODEL, HDIM, (long long)DMODEL * HDIM, (long long)HDIM * DMODEL);
        transpose_k<<<dim3(2, 32, 16), dim3(32, 8)>>>(wtk, Wk + l * WQKV_L,
            DMODEL, HDIM, (long long)DMODEL * HDIM, (long long)HDIM * DMODEL);
        transpose_k<<<dim3(2, 32, 16), dim3(32, 8)>>>(wtv, Wv + l * WQKV_L,
            DMODEL, HDIM, (long long)DMODEL * HDIM, (long long)HDIM * DMODEL);
        transpose_k<<<dim3(32, 32, 1), dim3(32, 8)>>>(wto, Wo + l * WO_L,
            DMODEL, DMODEL, 0, 0);
        transpose_k<<<dim3(FFDIM / 32, DMODEL / 32, 1), dim3(32, 8)>>>(wt1, W1 + l * W1_L,
            DMODEL, FFDIM, 0, 0);
        transpose_k<<<dim3(DMODEL / 32, FFDIM / 32, 1), dim3(32, 8)>>>(wt2, W2 + l * W2_L,
            FFDIM, DMODEL, 0, 0);

        // q = h @ Wq + bq ; k = h @ Wk + bk  (A=activations cvt, B=weights pre-rounded)
        gemm(1, 0, h, 0, 0, DMODEL, wtq, 0, 0, DMODEL, q, 0, 0, DMODEL,
             bq_l, 0, 0, 0, NTOK, DMODEL, DMODEL, 1.f, 1, 1, 0);
        gemm(1, 0, h, 0, 0, DMODEL, wtk, 0, 0, DMODEL, k, 0, 0, DMODEL,
             bk_l, 0, 0, 0, NTOK, DMODEL, DMODEL, 1.f, 1, 1, 0);
        // v_t = WvT @ h^T (+ bv per row): A=weights(pre-rounded), B=h(cvt)
        gemm(0, 1, wtv, 0, 0, DMODEL, h, 0, 0, DMODEL, vt, 0, 0, NTOK,
             bv_l, 0, 0, 1, DMODEL, NTOK, DMODEL, 1.f, 1, 1, 0);

        flash_attn<<<dim3(8, 64), 256, 204800>>>(q, k, vt, o);

        gemm(1, 0, o, 0, 0, DMODEL, wto, 0, 0, DMODEL, tmp, 0, 0, DMODEL,
             bo_l, 0, 0, 0, NTOK, DMODEL, DMODEL, 1.f, 1, 1, 0);

        add_ln<<<NTOK, 256>>>(h, tmp, ln1w + l * DMODEL, ln1b + l * DMODEL);

        // FFN: W1 (gelu fused, output pre-rounded), W2 (no cvt at all)
        gemm(1, 0, h, 0, 0, DMODEL, wt1, 0, 0, DMODEL, f1, 0, 0, FFDIM,
             b1_l, 0, 0, 0, NTOK, FFDIM, DMODEL, 1.f, 1, 1, 1);
        gemm(0, 0, f1, 0, 0, FFDIM, wt2, 0, 0, FFDIM, tmp, 0, 0, DMODEL,
             b2_l, 0, 0, 0, NTOK, DMODEL, FFDIM, 1.f, 1, 1, 0);

        add_ln<<<NTOK, 256>>>(h, tmp, ln2w + l * DMODEL, ln2b + l * DMODEL);
    }

    gemm(1, 0, h, 0, 0, DMODEL, wtout, 0, 0, DMODEL, out, 0, 0, VOCAB,
         bout, 0, 0, 0, NTOK, VOCAB, DMODEL, 1.f, 1, 1, 0);

    copy_kernel<<<(NTOK * DMODEL) / 1024, 256>>>(out + (long long)NTOK * VOCAB, h);
}

// round 6
// speedup vs baseline: 7.0711x; 1.8291x over previous
#include <cuda_runtime.h>
#include <cuda_fp16.h>
#include <cstdint>

// GPT_78932908966066 — Round 6: fp16 m16n8k16 mma.sync everywhere (same 10-bit
// mantissa as tf32, 2x tensor rate), fp32 accumulate. Flash attention in fp16.
// L=2, H=16, D=1024, HD=64, FF=4096, V=32000, S=1024, B=4.

#define NTOK   4096
#define DMODEL 1024
#define NHEAD  16
#define HDIM   64
#define FFDIM  4096
#define VOCAB  32000
#define SEQ    1024
#define NLAYER 2

// ---------------- static scratch ----------------
__device__ float  g_h   [NTOK * DMODEL];
__device__ __half g_h16 [NTOK * DMODEL];
__device__ __half g_q16 [NTOK * DMODEL];
__device__ __half g_k16 [NTOK * DMODEL];
__device__ __half g_vt16[DMODEL * NTOK];
__device__ __half g_o16 [NTOK * DMODEL];
__device__ float  g_tmp [NTOK * DMODEL];
__device__ __half g_f116[NTOK * FFDIM];
__device__ __half g_wtq [DMODEL * DMODEL];
__device__ __half g_wtk [DMODEL * DMODEL];
__device__ __half g_wtv [DMODEL * DMODEL];
__device__ __half g_wto [DMODEL * DMODEL];
__device__ __half g_wt1 [FFDIM * DMODEL];
__device__ __half g_wt2 [DMODEL * FFDIM];
__device__ __half g_wtout[(size_t)VOCAB * DMODEL];
__device__ int    g_is64;

// ---------------- helpers ----------------
__device__ __forceinline__ uint32_t smem_u32(const void* p) {
    uint32_t a;
    asm("{ .reg .u64 t; cvta.to.shared.u64 t, %1; cvt.u32.u64 %0, t; }" : "=r"(a) : "l"(p));
    return a;
}
__device__ __forceinline__ void cpasync16(uint32_t dst, const void* src) {
    asm volatile("cp.async.cg.shared.global [%0], [%1], 16;" :: "r"(dst), "l"(src) : "memory");
}
__device__ __forceinline__ void cp_commit() {
    asm volatile("cp.async.commit_group;" ::: "memory");
}
__device__ __forceinline__ void mma_f16(float* c, const uint32_t* a, const uint32_t* b) {
    asm volatile(
        "mma.sync.aligned.m16n8k16.row.col.f32.f16.f16.f32 "
        "{%0,%1,%2,%3}, {%4,%5,%6,%7}, {%8,%9}, {%0,%1,%2,%3};"
        : "+f"(c[0]), "+f"(c[1]), "+f"(c[2]), "+f"(c[3])
        : "r"(a[0]), "r"(a[1]), "r"(a[2]), "r"(a[3]), "r"(b[0]), "r"(b[1]));
}
__device__ __forceinline__ uint32_t lds32(const char* base, int off) {
    return *(const uint32_t*)(base + off);
}

// ---------------- fp16 NT GEMM: 256x128 CTA tile, 8 warps (64x64 each) ----------
// C[m,n] = alpha * sum_k A[m,k]*B[n,k] (+ bias, opt GELU). K multiple of 64.
// smem row = 64 halves (128B) + 16B pad = 144B.
template<int CHALF>
__global__ void __launch_bounds__(256, 1) gemm_h(
    const __half* __restrict__ A, long long aO, long long aI, int lda,
    const __half* __restrict__ B, long long bO, long long bI, int ldb,
    void* __restrict__ Cv, long long cO, long long cI, int ldc,
    const float* __restrict__ bias, long long biasO, long long biasI, int biasRow,
    int K, float alpha, int bdiv, int gelu)
{
    constexpr int ASTG = 256 * 144;      // bytes per A stage
    constexpr int BSTG = 128 * 144;      // bytes per B stage

    extern __shared__ char sm[];
    const int rowBase = blockIdx.y * 256;
    const int colBase = blockIdx.x * 128;

    const int z = blockIdx.z;
    const int zo = z / bdiv, zi = z - zo * bdiv;
    A += zo * aO + zi * aI + (long long)rowBase * lda;
    B += zo * bO + zi * bI + (long long)colBase * ldb;
    if (bias) bias += zo * biasO + zi * biasI;

    const int tid = threadIdx.x;
    const int wid = tid >> 5, lane = tid & 31;
    const int gid = lane >> 2, tig = lane & 3;
    const int warpM = wid & 3, warpN = wid >> 2;

    char* smB = sm + 3 * ASTG;
    const uint32_t smA_u = smem_u32(sm);
    const uint32_t smB_u = smem_u32(smB);

    const int nk = K >> 6;

    auto load_stage = [&](int s, int i) {
        const int k0 = i << 6;
        uint32_t ab = smA_u + (uint32_t)s * ASTG;
        #pragma unroll
        for (int c = 0; c < 8; c++) {                 // 2048 chunks / 256 thr
            int idx = tid + c * 256;
            int row = idx >> 3, part = idx & 7;
            cpasync16(ab + row * 144 + part * 16, A + (long long)row * lda + k0 + part * 8);
        }
        uint32_t bb = smB_u + (uint32_t)s * BSTG;
        #pragma unroll
        for (int c = 0; c < 4; c++) {                 // 1024 chunks / 256 thr
            int idx = tid + c * 256;
            int row = idx >> 3, part = idx & 7;
            cpasync16(bb + row * 144 + part * 16, B + (long long)row * ldb + k0 + part * 8);
        }
    };

    float acc[4][8][4];
    #pragma unroll
    for (int mt = 0; mt < 4; mt++)
        #pragma unroll
        for (int nt = 0; nt < 8; nt++)
            #pragma unroll
            for (int r = 0; r < 4; r++) acc[mt][nt][r] = 0.f;

    load_stage(0, 0); cp_commit();
    if (nk > 1) load_stage(1, 1);
    cp_commit();

    for (int i = 0; i < nk; i++) {
        if (i + 2 < nk) load_stage((i + 2) % 3, i + 2);
        cp_commit();
        asm volatile("cp.async.wait_group 2;" ::: "memory");
        __syncthreads();

        const char* as = sm  + (i % 3) * ASTG;
        const char* bs = smB + (i % 3) * BSTG;
        #pragma unroll
        for (int kk = 0; kk < 4; kk++) {              // 4 x k16
            uint32_t af[4][4], bf[8][2];
            #pragma unroll
            for (int mt = 0; mt < 4; mt++) {
                int ro = (warpM * 64 + mt * 16 + gid) * 144 + kk * 32 + tig * 4;
                af[mt][0] = lds32(as, ro);
                af[mt][1] = lds32(as, ro + 8 * 144);
                af[mt][2] = lds32(as, ro + 16);
                af[mt][3] = lds32(as, ro + 8 * 144 + 16);
            }
            #pragma unroll
            for (int nt = 0; nt < 8; nt++) {
                int ro = (warpN * 64 + nt * 8 + gid) * 144 + kk * 32 + tig * 4;
                bf[nt][0] = lds32(bs, ro);
                bf[nt][1] = lds32(bs, ro + 16);
            }
            #pragma unroll
            for (int mt = 0; mt < 4; mt++)
                #pragma unroll
                for (int nt = 0; nt < 8; nt++)
                    mma_f16(acc[mt][nt], af[mt], bf[nt]);
        }
        __syncthreads();
    }

    #pragma unroll
    for (int mt = 0; mt < 4; mt++) {
        #pragma unroll
        for (int nt = 0; nt < 8; nt++) {
            int row0 = rowBase + warpM * 64 + mt * 16 + gid;
            int col0 = colBase + warpN * 64 + nt * 8 + tig * 2;
            float b0 = 0.f, b1 = 0.f;
            if (bias && !biasRow) { b0 = bias[col0]; b1 = bias[col0 + 1]; }
            #pragma unroll
            for (int hh = 0; hh < 2; hh++) {
                int row = row0 + hh * 8;
                float rb = (bias && biasRow) ? bias[row] : 0.f;
                float v0 = alpha * acc[mt][nt][hh * 2 + 0] + b0 + rb;
                float v1 = alpha * acc[mt][nt][hh * 2 + 1] + b1 + rb;
                if (gelu) {
                    v0 = 0.5f * v0 * (1.f + erff(v0 * 0.70710678118654752f));
                    v1 = 0.5f * v1 * (1.f + erff(v1 * 0.70710678118654752f));
                }
                if (CHALF) {
                    __half2* C = (__half2*)((__half*)Cv + zo * cO + zi * cI);
                    C[((long long)row * ldc + col0) >> 1] = __floats2half2_rn(v0, v1);
                } else {
                    float* C = (float*)Cv + zo * cO + zi * cI;
                    *(float2*)(C + (long long)row * ldc + col0) = make_float2(v0, v1);
                }
            }
        }
    }
}

// ---------------- fused flash attention (fp16 operands, fp32 softmax) ----------
// grid (8 q-tiles, 64 z=b*16+h), 256 threads (8 warps x 16 q-rows).
__global__ void __launch_bounds__(256, 1) flash_attn(
    const __half* __restrict__ q, const __half* __restrict__ k,
    const __half* __restrict__ vt, __half* __restrict__ og)
{
    extern __shared__ char sm[];
    // bytes: K double buf 2x(128*144)=36864, V 2x(64*272)=34816, P 128*272=34816
    constexpr int KS0 = 0, KS1 = 18432, VS0 = 36864, VS1 = 54272, PS = 71680;

    const int qi = blockIdx.x;
    const int z  = blockIdx.y;
    const int b  = z >> 4, hh = z & 15;
    const int hcol = hh * 64;
    const int qtok0 = b * 1024 + qi * 128;

    const int tid = threadIdx.x;
    const int w = tid >> 5, lane = tid & 31;
    const int gid = lane >> 2, tig = lane & 3;

    const uint32_t sbase = smem_u32(sm);

    // Q fragments (scaled by 1/8), register resident: 4 x k16
    uint32_t qf[4][4];
    {
        const __half2 sc8 = __floats2half2_rn(0.125f, 0.125f);
        const __half* qb = q + (long long)(qtok0 + w * 16) * 1024 + hcol;
        #pragma unroll
        for (int kk = 0; kk < 4; kk++) {
            __half2 x0 = __hmul2(*(const __half2*)(qb + gid * 1024 + kk * 16 + tig * 2), sc8);
            __half2 x1 = __hmul2(*(const __half2*)(qb + (gid + 8) * 1024 + kk * 16 + tig * 2), sc8);
            __half2 x2 = __hmul2(*(const __half2*)(qb + gid * 1024 + kk * 16 + tig * 2 + 8), sc8);
            __half2 x3 = __hmul2(*(const __half2*)(qb + (gid + 8) * 1024 + kk * 16 + tig * 2 + 8), sc8);
            qf[kk][0] = *(uint32_t*)&x0; qf[kk][1] = *(uint32_t*)&x1;
            qf[kk][2] = *(uint32_t*)&x2; qf[kk][3] = *(uint32_t*)&x3;
        }
    }

    float oa[8][4];
    #pragma unroll
    for (int nt = 0; nt < 8; nt++)
        #pragma unroll
        for (int r = 0; r < 4; r++) oa[nt][r] = 0.f;
    float m_l = -1e30f, m_h = -1e30f, l_l = 0.f, l_h = 0.f;

    auto load_kv = [&](int j, int buf) {
        const __half* kb = k + (long long)(b * 1024 + j * 128) * 1024 + hcol;
        uint32_t kd = sbase + (buf ? KS1 : KS0);
        #pragma unroll
        for (int c = 0; c < 4; c++) {                 // 128 rows x 8 chunks
            int idx = tid + c * 256;
            int row = idx >> 3, part = idx & 7;
            cpasync16(kd + row * 144 + part * 16, kb + (long long)row * 1024 + part * 8);
        }
        const __half* vb = vt + (long long)hcol * 4096 + b * 1024 + j * 128;
        uint32_t vd = sbase + (buf ? VS1 : VS0);
        #pragma unroll
        for (int c = 0; c < 4; c++) {                 // 64 rows x 16 chunks
            int idx = tid + c * 256;
            int row = idx >> 4, part = idx & 15;
            cpasync16(vd + row * 272 + part * 16, vb + (long long)row * 4096 + part * 8);
        }
    };

    load_kv(0, 0);
    cp_commit();

    for (int j = 0; j <= qi; j++) {
        const int buf = j & 1;
        __syncthreads();
        if (j < qi) load_kv(j + 1, buf ^ 1);
        cp_commit();
        asm volatile("cp.async.wait_group 1;" ::: "memory");
        __syncthreads();

        const char* Ks = sm + (buf ? KS1 : KS0);
        const char* Vs = sm + (buf ? VS1 : VS0);
        char* Psm = sm + PS;

        // S = (Q/8) K^T : warp computes 16 x 128
        float sa[16][4];
        #pragma unroll
        for (int nt = 0; nt < 16; nt++)
            #pragma unroll
            for (int r = 0; r < 4; r++) sa[nt][r] = 0.f;
        #pragma unroll
        for (int kk = 0; kk < 4; kk++) {
            #pragma unroll
            for (int nt = 0; nt < 16; nt++) {
                int ro = (nt * 8 + gid) * 144 + kk * 32 + tig * 4;
                uint32_t bf[2] = { lds32(Ks, ro), lds32(Ks, ro + 16) };
                mma_f16(sa[nt], qf[kk], bf);
            }
        }

        if (j == qi) {      // causal mask on diagonal tile
            int rl = w * 16 + gid, rh = rl + 8;
            #pragma unroll
            for (int nt = 0; nt < 16; nt++) {
                int c0 = nt * 8 + tig * 2, c1 = c0 + 1;
                if (c0 > rl) sa[nt][0] = -1e30f;
                if (c1 > rl) sa[nt][1] = -1e30f;
                if (c0 > rh) sa[nt][2] = -1e30f;
                if (c1 > rh) sa[nt][3] = -1e30f;
            }
        }

        // online softmax
        float mxl = -1e30f, mxh = -1e30f;
        #pragma unroll
        for (int nt = 0; nt < 16; nt++) {
            mxl = fmaxf(mxl, fmaxf(sa[nt][0], sa[nt][1]));
            mxh = fmaxf(mxh, fmaxf(sa[nt][2], sa[nt][3]));
        }
        mxl = fmaxf(mxl, __shfl_xor_sync(0xffffffffu, mxl, 1));
        mxl = fmaxf(mxl, __shfl_xor_sync(0xffffffffu, mxl, 2));
        mxh = fmaxf(mxh, __shfl_xor_sync(0xffffffffu, mxh, 1));
        mxh = fmaxf(mxh, __shfl_xor_sync(0xffffffffu, mxh, 2));
        float nml = fmaxf(m_l, mxl), nmh = fmaxf(m_h, mxh);
        float cl = __expf(m_l - nml), ch = __expf(m_h - nmh);
        m_l = nml; m_h = nmh;

        float sl = 0.f, sh = 0.f;
        #pragma unroll
        for (int nt = 0; nt < 16; nt++) {
            float p0 = __expf(sa[nt][0] - m_l);
            float p1 = __expf(sa[nt][1] - m_l);
            float p2 = __expf(sa[nt][2] - m_h);
            float p3 = __expf(sa[nt][3] - m_h);
            sl += p0 + p1; sh += p2 + p3;
            int co = (nt * 8 + tig * 2) * 2;
            *(__half2*)(Psm + (w * 16 + gid) * 272 + co) = __floats2half2_rn(p0, p1);
            *(__half2*)(Psm + (w * 16 + gid + 8) * 272 + co) = __floats2half2_rn(p2, p3);
        }
        sl += __shfl_xor_sync(0xffffffffu, sl, 1);
        sl += __shfl_xor_sync(0xffffffffu, sl, 2);
        sh += __shfl_xor_sync(0xffffffffu, sh, 1);
        sh += __shfl_xor_sync(0xffffffffu, sh, 2);
        l_l = l_l * cl + sl;
        l_h = l_h * ch + sh;
        #pragma unroll
        for (int nt = 0; nt < 8; nt++) {
            oa[nt][0] *= cl; oa[nt][1] *= cl;
            oa[nt][2] *= ch; oa[nt][3] *= ch;
        }
        __syncwarp();   // P rows are warp-private

        // O += P V^T : kk over 128 keys / 16
        #pragma unroll
        for (int kk = 0; kk < 8; kk++) {
            int po = (w * 16 + gid) * 272 + kk * 32 + tig * 4;
            uint32_t af[4] = { lds32(Psm, po), lds32(Psm, po + 8 * 272),
                               lds32(Psm, po + 16), lds32(Psm, po + 8 * 272 + 16) };
            #pragma unroll
            for (int nt = 0; nt < 8; nt++) {
                int vo = (nt * 8 + gid) * 272 + kk * 32 + tig * 4;
                uint32_t bf[2] = { lds32(Vs, vo), lds32(Vs, vo + 16) };
                mma_f16(oa[nt], af, bf);
            }
        }
    }

    float il = 1.f / l_l, ih = 1.f / l_h;
    #pragma unroll
    for (int nt = 0; nt < 8; nt++) {
        long long r0 = qtok0 + w * 16 + gid;
        int c0 = hcol + nt * 8 + tig * 2;
        *(__half2*)(og + r0 * 1024 + c0) = __floats2half2_rn(oa[nt][0] * il, oa[nt][1] * il);
        *(__half2*)(og + (r0 + 8) * 1024 + c0) = __floats2half2_rn(oa[nt][2] * ih, oa[nt][3] * ih);
    }
}

// ---------------- transpose fp32 -> fp16 [N,K] ----------------
__global__ void __launch_bounds__(256) transpose_k(
    __half* __restrict__ dst, const float* __restrict__ src,
    int R, int Cc, long long srcBatch, long long dstBatch)
{
    __shared__ float t[32][33];
    src += (long long)blockIdx.z * srcBatch;
    dst += (long long)blockIdx.z * dstBatch;
    int c0 = blockIdx.x * 32, r0 = blockIdx.y * 32;
    int x = threadIdx.x, y = threadIdx.y;
    #pragma unroll
    for (int j = 0; j < 32; j += 8)
        t[y + j][x] = src[(long long)(r0 + y + j) * Cc + c0 + x];
    __syncthreads();
    #pragma unroll
    for (int j = 0; j < 32; j += 8)
        dst[(long long)(c0 + y + j) * R + r0 + x] = __float2half(t[x][y + j]);
}

// ---------------- token width detect ----------------
__global__ void detect64_kernel(const int* __restrict__ x32) {
    __shared__ int red[256];
    int o = 0;
    for (int i = threadIdx.x; i < 2048; i += 256) o |= x32[2 * i + 1];
    red[threadIdx.x] = o; __syncthreads();
    for (int st = 128; st > 0; st >>= 1) {
        if (threadIdx.x < st) red[threadIdx.x] |= red[threadIdx.x + st];
        __syncthreads();
    }
    if (threadIdx.x == 0) g_is64 = (red[0] == 0) ? 1 : 0;
}

// ---------------- embedding (fp32 + fp16 copies) ----------------
__global__ __launch_bounds__(256) void embed_kernel(
    const int* __restrict__ x32, const float* __restrict__ tok,
    const float* __restrict__ pos, float* __restrict__ h, __half* __restrict__ h16)
{
    int t = blockIdx.x;
    long long id = g_is64 ? ((const long long*)x32)[t] : (long long)x32[t];
    int s = t & (SEQ - 1);
    const float* tr = tok + id * DMODEL;
    const float* pr = pos + (long long)s * DMODEL;
    long long base = (long long)t * DMODEL;
    for (int i = threadIdx.x; i < DMODEL; i += 256) {
        float v = tr[i] + pr[i];
        h[base + i] = v;
        h16[base + i] = __float2half(v);
    }
}

// ---------------- residual + LayerNorm (fp32, emits fp16 copy) ----------------
__global__ __launch_bounds__(256) void add_ln(
    float* __restrict__ h, __half* __restrict__ h16, const float* __restrict__ t,
    const float* __restrict__ w, const float* __restrict__ b)
{
    __shared__ float buf[DMODEL];
    __shared__ float red[256];
    long long base = (long long)blockIdx.x * DMODEL;
    int tid = threadIdx.x;

    float s = 0.f;
    for (int i = tid; i < DMODEL; i += 256) {
        float x = h[base + i] + t[base + i];
        buf[i] = x; s += x;
    }
    red[tid] = s; __syncthreads();
    for (int st = 128; st > 0; st >>= 1) {
        if (tid < st) red[tid] += red[tid + st];
        __syncthreads();
    }
    float mean = red[0] * (1.f / DMODEL); __syncthreads();

    float s2 = 0.f;
    for (int i = tid; i < DMODEL; i += 256) { float d = buf[i] - mean; s2 += d * d; }
    red[tid] = s2; __syncthreads();
    for (int st = 128; st > 0; st >>= 1) {
        if (tid < st) red[tid] += red[tid + st];
        __syncthreads();
    }
    float inv = rsqrtf(red[0] * (1.f / DMODEL) + 1e-5f);
    for (int i = tid; i < DMODEL; i += 256) {
        float v = (buf[i] - mean) * inv * w[i] + b[i];
        h[base + i] = v;
        h16[base + i] = __float2half(v);
    }
}

__global__ __launch_bounds__(256) void copy_kernel(float* __restrict__ dst,
                                                   const float* __restrict__ src)
{
    long long i = ((long long)blockIdx.x * 256 + threadIdx.x) * 4;
    *(float4*)(dst + i) = *(const float4*)(src + i);
}

// ---------------- host side ----------------
#define GEMM_SMEM (3 * (256 * 144 + 128 * 144))   // 165888
#define FA_SMEM   106496

static void gemm(int chalf,
                 const __half* A, long long aO, long long aI, int lda,
                 const __half* B, long long bO, long long bI, int ldb,
                 void* C, long long cO, long long cI, int ldc,
                 const float* bias, long long biasO, long long biasI, int biasRow,
                 int M, int N, int K, float alpha, int bdiv, int batches, int gelu)
{
    dim3 g(N / 128, M / 256, batches);
    if (chalf)
        gemm_h<1><<<g, 256, GEMM_SMEM>>>(A, aO, aI, lda, B, bO, bI, ldb, C, cO, cI, ldc,
                                         bias, biasO, biasI, biasRow, K, alpha, bdiv, gelu);
    else
        gemm_h<0><<<g, 256, GEMM_SMEM>>>(A, aO, aI, lda, B, bO, bI, ldb, C, cO, cI, ldc,
                                         bias, biasO, biasI, biasRow, K, alpha, bdiv, gelu);
}

extern "C" void kernel_launch(void* const* d_in, const int* in_sizes, int n_in,
                              void* d_out, int out_size)
{
    const int*   x32     = (const int*)  d_in[0];
    const float* tok_emb = (const float*)d_in[1];
    const float* pos_emb = (const float*)d_in[2];
    const float* Wq      = (const float*)d_in[3];
    const float* bq      = (const float*)d_in[4];
    const float* Wk      = (const float*)d_in[5];
    const float* bk      = (const float*)d_in[6];
    const float* Wv      = (const float*)d_in[7];
    const float* bv      = (const float*)d_in[8];
    const float* Wo      = (const float*)d_in[9];
    const float* bo      = (const float*)d_in[10];
    const float* ln1w    = (const float*)d_in[11];
    const float* ln1b    = (const float*)d_in[12];
    const float* ln2w    = (const float*)d_in[13];
    const float* ln2b    = (const float*)d_in[14];
    const float* W1      = (const float*)d_in[15];
    const float* b1      = (const float*)d_in[16];
    const float* W2      = (const float*)d_in[17];
    const float* b2      = (const float*)d_in[18];
    const float* Wout    = (const float*)d_in[19];
    const float* bout    = (const float*)d_in[20];
    float* out = (float*)d_out;

    float *h, *tmp;
    __half *h16, *q16, *k16, *vt16, *o16, *f116;
    __half *wtq, *wtk, *wtv, *wto, *wt1, *wt2, *wtout;
    cudaGetSymbolAddress((void**)&h,    g_h);
    cudaGetSymbolAddress((void**)&h16,  g_h16);
    cudaGetSymbolAddress((void**)&q16,  g_q16);
    cudaGetSymbolAddress((void**)&k16,  g_k16);
    cudaGetSymbolAddress((void**)&vt16, g_vt16);
    cudaGetSymbolAddress((void**)&o16,  g_o16);
    cudaGetSymbolAddress((void**)&tmp,  g_tmp);
    cudaGetSymbolAddress((void**)&f116, g_f116);
    cudaGetSymbolAddress((void**)&wtq,  g_wtq);
    cudaGetSymbolAddress((void**)&wtk,  g_wtk);
    cudaGetSymbolAddress((void**)&wtv,  g_wtv);
    cudaGetSymbolAddress((void**)&wto,  g_wto);
    cudaGetSymbolAddress((void**)&wt1,  g_wt1);
    cudaGetSymbolAddress((void**)&wt2,  g_wt2);
    cudaGetSymbolAddress((void**)&wtout, g_wtout);

    cudaFuncSetAttribute(gemm_h<0>, cudaFuncAttributeMaxDynamicSharedMemorySize, GEMM_SMEM);
    cudaFuncSetAttribute(gemm_h<1>, cudaFuncAttributeMaxDynamicSharedMemorySize, GEMM_SMEM);
    cudaFuncSetAttribute(flash_attn, cudaFuncAttributeMaxDynamicSharedMemorySize, FA_SMEM);

    detect64_kernel<<<1, 256>>>(x32);
    embed_kernel<<<NTOK, 256>>>(x32, tok_emb, pos_emb, h, h16);

    transpose_k<<<dim3(VOCAB / 32, DMODEL / 32, 1), dim3(32, 8)>>>(
        wtout, Wout, DMODEL, VOCAB, 0, 0);

    const long long WQKV_L = (long long)NHEAD * DMODEL * HDIM;
    const long long BQKV_L = (long long)NHEAD * HDIM;
    const long long WO_L   = (long long)DMODEL * DMODEL;
    const long long W1_L   = (long long)DMODEL * FFDIM;
    const long long W2_L   = (long long)FFDIM * DMODEL;

    for (int l = 0; l < NLAYER; l++) {
        const float* bq_l = bq + l * BQKV_L;
        const float* bk_l = bk + l * BQKV_L;
        const float* bv_l = bv + l * BQKV_L;
        const float* bo_l = bo + l * DMODEL;
        const float* b1_l = b1 + l * FFDIM;
        const float* b2_l = b2 + l * DMODEL;

        transpose_k<<<dim3(2, 32, 16), dim3(32, 8)>>>(wtq, Wq + l * WQKV_L,
            DMODEL, HDIM, (long long)DMODEL * HDIM, (long long)HDIM * DMODEL);
        transpose_k<<<dim3(2, 32, 16), dim3(32, 8)>>>(wtk, Wk + l * WQKV_L,
            DMODEL, HDIM, (long long)DMODEL * HDIM, (long long)HDIM * DMODEL);
        transpose_k<<<dim3(2, 32, 16), dim3(32, 8)>>>(wtv, Wv + l * WQKV_L,
            DMODEL, HDIM, (long long)DMODEL * HDIM, (long long)HDIM * DMODEL);
        transpose_k<<<dim3(32, 32, 1), dim3(32, 8)>>>(wto, Wo + l * WO_L,
            DMODEL, DMODEL, 0, 0);
        transpose_k<<<dim3(FFDIM / 32, DMODEL / 32, 1), dim3(32, 8)>>>(wt1, W1 + l * W1_L,
            DMODEL, FFDIM, 0, 0);
        transpose_k<<<dim3(DMODEL / 32, FFDIM / 32, 1), dim3(32, 8)>>>(wt2, W2 + l * W2_L,
            FFDIM, DMODEL, 0, 0);

        // q = h @ Wq + bq ; k = h @ Wk + bk  (fp16 out)
        gemm(1, h16, 0, 0, DMODEL, wtq, 0, 0, DMODEL, q16, 0, 0, DMODEL,
             bq_l, 0, 0, 0, NTOK, DMODEL, DMODEL, 1.f, 1, 1, 0);
        gemm(1, h16, 0, 0, DMODEL, wtk, 0, 0, DMODEL, k16, 0, 0, DMODEL,
             bk_l, 0, 0, 0, NTOK, DMODEL, DMODEL, 1.f, 1, 1, 0);
        // v_t = WvT @ h^T (+ bv per row), fp16 out
        gemm(1, wtv, 0, 0, DMODEL, h16, 0, 0, DMODEL, vt16, 0, 0, NTOK,
             bv_l, 0, 0, 1, DMODEL, NTOK, DMODEL, 1.f, 1, 1, 0);

        flash_attn<<<dim3(8, 64), 256, FA_SMEM>>>(q16, k16, vt16, o16);

        // attn projection -> fp32 tmp
        gemm(0, o16, 0, 0, DMODEL, wto, 0, 0, DMODEL, tmp, 0, 0, DMODEL,
             bo_l, 0, 0, 0, NTOK, DMODEL, DMODEL, 1.f, 1, 1, 0);

        add_ln<<<NTOK, 256>>>(h, h16, tmp, ln1w + l * DMODEL, ln1b + l * DMODEL);

        // FFN: W1 (gelu fused, fp16 out), W2 (fp32 out)
        gemm(1, h16, 0, 0, DMODEL, wt1, 0, 0, DMODEL, f116, 0, 0, FFDIM,
             b1_l, 0, 0, 0, NTOK, FFDIM, DMODEL, 1.f, 1, 1, 1);
        gemm(0, f116, 0, 0, FFDIM, wt2, 0, 0, FFDIM, tmp, 0, 0, DMODEL,
             b2_l, 0, 0, 0, NTOK, DMODEL, FFDIM, 1.f, 1, 1, 0);

        add_ln<<<NTOK, 256>>>(h, h16, tmp, ln2w + l * DMODEL, ln2b + l * DMODEL);
    }

    // logits (fp32 out)
    gemm(0, h16, 0, 0, DMODEL, wtout, 0, 0, DMODEL, out, 0, 0, VOCAB,
         bout, 0, 0, 0, NTOK, VOCAB, DMODEL, 1.f, 1, 1, 0);

    copy_kernel<<<(NTOK * DMODEL) / 1024, 256>>>(out + (long long)NTOK * VOCAB, h);
}

// round 8
// speedup vs baseline: 7.0854x; 1.0020x over previous
#include <cuda_runtime.h>
#include <cuda_fp16.h>
#include <cstdint>

// GPT_78932908966066 — Round 7: ldmatrix.x4 fragment loads (4x fewer shared-pipe
// ops) in both the fp16 GEMM mainloop and flash attention. fp32 accumulate.
// L=2, H=16, D=1024, HD=64, FF=4096, V=32000, S=1024, B=4.

#define NTOK   4096
#define DMODEL 1024
#define NHEAD  16
#define HDIM   64
#define FFDIM  4096
#define VOCAB  32000
#define SEQ    1024
#define NLAYER 2

// ---------------- static scratch ----------------
__device__ float  g_h   [NTOK * DMODEL];
__device__ __half g_h16 [NTOK * DMODEL];
__device__ __half g_q16 [NTOK * DMODEL];
__device__ __half g_k16 [NTOK * DMODEL];
__device__ __half g_vt16[DMODEL * NTOK];
__device__ __half g_o16 [NTOK * DMODEL];
__device__ float  g_tmp [NTOK * DMODEL];
__device__ __half g_f116[NTOK * FFDIM];
__device__ __half g_wtq [DMODEL * DMODEL];
__device__ __half g_wtk [DMODEL * DMODEL];
__device__ __half g_wtv [DMODEL * DMODEL];
__device__ __half g_wto [DMODEL * DMODEL];
__device__ __half g_wt1 [FFDIM * DMODEL];
__device__ __half g_wt2 [DMODEL * FFDIM];
__device__ __half g_wtout[(size_t)VOCAB * DMODEL];
__device__ int    g_is64;

// ---------------- helpers ----------------
__device__ __forceinline__ uint32_t smem_u32(const void* p) {
    uint32_t a;
    asm("{ .reg .u64 t; cvta.to.shared.u64 t, %1; cvt.u32.u64 %0, t; }" : "=r"(a) : "l"(p));
    return a;
}
__device__ __forceinline__ void cpasync16(uint32_t dst, const void* src) {
    asm volatile("cp.async.cg.shared.global [%0], [%1], 16;" :: "r"(dst), "l"(src) : "memory");
}
__device__ __forceinline__ void cp_commit() {
    asm volatile("cp.async.commit_group;" ::: "memory");
}
__device__ __forceinline__ void mma_f16(float* c, const uint32_t* a, const uint32_t* b) {
    asm volatile(
        "mma.sync.aligned.m16n8k16.row.col.f32.f16.f16.f32 "
        "{%0,%1,%2,%3}, {%4,%5,%6,%7}, {%8,%9}, {%0,%1,%2,%3};"
        : "+f"(c[0]), "+f"(c[1]), "+f"(c[2]), "+f"(c[3])
        : "r"(a[0]), "r"(a[1]), "r"(a[2]), "r"(a[3]), "r"(b[0]), "r"(b[1]));
}
__device__ __forceinline__ void ldsm_x4(uint32_t& r0, uint32_t& r1, uint32_t& r2,
                                        uint32_t& r3, uint32_t addr) {
    asm volatile("ldmatrix.sync.aligned.m8n8.x4.shared.b16 {%0,%1,%2,%3}, [%4];"
                 : "=r"(r0), "=r"(r1), "=r"(r2), "=r"(r3) : "r"(addr));
}

// ---------------- fp16 NT GEMM: 256x128 CTA tile, 8 warps (64x64 each) ----------
// C[m,n] = alpha * sum_k A[m,k]*B[n,k] (+ bias, opt GELU). K multiple of 64.
// smem row = 64 halves (128B) + 16B pad = 144B. Fragments via ldmatrix.x4.
template<int CHALF>
__global__ void __launch_bounds__(256, 1) gemm_h(
    const __half* __restrict__ A, long long aO, long long aI, int lda,
    const __half* __restrict__ B, long long bO, long long bI, int ldb,
    void* __restrict__ Cv, long long cO, long long cI, int ldc,
    const float* __restrict__ bias, long long biasO, long long biasI, int biasRow,
    int K, float alpha, int bdiv, int gelu)
{
    constexpr int ASTG = 256 * 144;
    constexpr int BSTG = 128 * 144;

    extern __shared__ char sm[];
    const int rowBase = blockIdx.y * 256;
    const int colBase = blockIdx.x * 128;

    const int z = blockIdx.z;
    const int zo = z / bdiv, zi = z - zo * bdiv;
    A += zo * aO + zi * aI + (long long)rowBase * lda;
    B += zo * bO + zi * bI + (long long)colBase * ldb;
    if (bias) bias += zo * biasO + zi * biasI;

    const int tid = threadIdx.x;
    const int wid = tid >> 5, lane = tid & 31;
    const int gid = lane >> 2, tig = lane & 3;
    const int warpM = wid & 3, warpN = wid >> 2;

    char* smB = sm + 3 * ASTG;
    const uint32_t smA_u = smem_u32(sm);
    const uint32_t smB_u = smem_u32(smB);

    // ldmatrix lane->address offsets (within a stage)
    const uint32_t aOff = (uint32_t)(warpM * 64 + (lane & 15)) * 144 + (lane >> 4) * 16;
    const uint32_t bOff = (uint32_t)(warpN * 64 + ((lane >> 4) * 8) + (lane & 7)) * 144
                        + ((lane >> 3) & 1) * 16;

    const int nk = K >> 6;

    auto load_stage = [&](int s, int i) {
        const int k0 = i << 6;
        uint32_t ab = smA_u + (uint32_t)s * ASTG;
        #pragma unroll
        for (int c = 0; c < 8; c++) {
            int idx = tid + c * 256;
            int row = idx >> 3, part = idx & 7;
            cpasync16(ab + row * 144 + part * 16, A + (long long)row * lda + k0 + part * 8);
        }
        uint32_t bb = smB_u + (uint32_t)s * BSTG;
        #pragma unroll
        for (int c = 0; c < 4; c++) {
            int idx = tid + c * 256;
            int row = idx >> 3, part = idx & 7;
            cpasync16(bb + row * 144 + part * 16, B + (long long)row * ldb + k0 + part * 8);
        }
    };

    float acc[4][8][4];
    #pragma unroll
    for (int mt = 0; mt < 4; mt++)
        #pragma unroll
        for (int nt = 0; nt < 8; nt++)
            #pragma unroll
            for (int r = 0; r < 4; r++) acc[mt][nt][r] = 0.f;

    load_stage(0, 0); cp_commit();
    if (nk > 1) load_stage(1, 1);
    cp_commit();

    for (int i = 0; i < nk; i++) {
        if (i + 2 < nk) load_stage((i + 2) % 3, i + 2);
        cp_commit();
        asm volatile("cp.async.wait_group 2;" ::: "memory");
        __syncthreads();

        const uint32_t aS = smA_u + (uint32_t)(i % 3) * ASTG + aOff;
        const uint32_t bS = smB_u + (uint32_t)(i % 3) * BSTG + bOff;
        #pragma unroll
        for (int kk = 0; kk < 4; kk++) {
            uint32_t af[4][4], bf[8][2];
            #pragma unroll
            for (int mt = 0; mt < 4; mt++)
                ldsm_x4(af[mt][0], af[mt][1], af[mt][2], af[mt][3],
                        aS + mt * (16 * 144) + kk * 32);
            #pragma unroll
            for (int p = 0; p < 4; p++)
                ldsm_x4(bf[2 * p][0], bf[2 * p][1], bf[2 * p + 1][0], bf[2 * p + 1][1],
                        bS + p * (16 * 144) + kk * 32);
            #pragma unroll
            for (int mt = 0; mt < 4; mt++)
                #pragma unroll
                for (int nt = 0; nt < 8; nt++)
                    mma_f16(acc[mt][nt], af[mt], bf[nt]);
        }
        __syncthreads();
    }

    #pragma unroll
    for (int mt = 0; mt < 4; mt++) {
        #pragma unroll
        for (int nt = 0; nt < 8; nt++) {
            int row0 = rowBase + warpM * 64 + mt * 16 + gid;
            int col0 = colBase + warpN * 64 + nt * 8 + tig * 2;
            float b0 = 0.f, b1 = 0.f;
            if (bias && !biasRow) { b0 = bias[col0]; b1 = bias[col0 + 1]; }
            #pragma unroll
            for (int hh = 0; hh < 2; hh++) {
                int row = row0 + hh * 8;
                float rb = (bias && biasRow) ? bias[row] : 0.f;
                float v0 = alpha * acc[mt][nt][hh * 2 + 0] + b0 + rb;
                float v1 = alpha * acc[mt][nt][hh * 2 + 1] + b1 + rb;
                if (gelu) {
                    v0 = 0.5f * v0 * (1.f + erff(v0 * 0.70710678118654752f));
                    v1 = 0.5f * v1 * (1.f + erff(v1 * 0.70710678118654752f));
                }
                if (CHALF) {
                    __half2* C = (__half2*)((__half*)Cv + zo * cO + zi * cI);
                    C[((long long)row * ldc + col0) >> 1] = __floats2half2_rn(v0, v1);
                } else {
                    float* C = (float*)Cv + zo * cO + zi * cI;
                    *(float2*)(C + (long long)row * ldc + col0) = make_float2(v0, v1);
                }
            }
        }
    }
}

// ---------------- fused flash attention (fp16, ldmatrix fragments) ----------
// grid (8 q-tiles, 64 z=b*16+h), 256 threads (8 warps x 16 q-rows).
__global__ void __launch_bounds__(256, 1) flash_attn(
    const __half* __restrict__ q, const __half* __restrict__ k,
    const __half* __restrict__ vt, __half* __restrict__ og)
{
    extern __shared__ char sm[];
    // bytes: K 2x(128*144)=36864, V 2x(64*272)=34816, P 128*272=34816
    constexpr int KS0 = 0, KS1 = 18432, VS0 = 36864, VS1 = 54272, PS = 71680;

    const int qi = blockIdx.x;
    const int z  = blockIdx.y;
    const int b  = z >> 4, hh = z & 15;
    const int hcol = hh * 64;
    const int qtok0 = b * 1024 + qi * 128;

    const int tid = threadIdx.x;
    const int w = tid >> 5, lane = tid & 31;
    const int gid = lane >> 2, tig = lane & 3;

    const uint32_t sbase = smem_u32(sm);

    // ldmatrix lane offsets
    const uint32_t kOffB = (uint32_t)(((lane >> 4) * 8) + (lane & 7)) * 144
                         + ((lane >> 3) & 1) * 16;                    // K (B-type, 144B)
    const uint32_t vOffB = (uint32_t)(((lane >> 4) * 8) + (lane & 7)) * 272
                         + ((lane >> 3) & 1) * 16;                    // V (B-type, 272B)
    const uint32_t pOffA = (uint32_t)(w * 16 + (lane & 15)) * 272 + (lane >> 4) * 16;  // P (A-type)

    // Q fragments (scaled by 1/8), register resident: 4 x k16
    uint32_t qf[4][4];
    {
        const __half2 sc8 = __floats2half2_rn(0.125f, 0.125f);
        const __half* qb = q + (long long)(qtok0 + w * 16) * 1024 + hcol;
        #pragma unroll
        for (int kk = 0; kk < 4; kk++) {
            __half2 x0 = __hmul2(*(const __half2*)(qb + gid * 1024 + kk * 16 + tig * 2), sc8);
            __half2 x1 = __hmul2(*(const __half2*)(qb + (gid + 8) * 1024 + kk * 16 + tig * 2), sc8);
            __half2 x2 = __hmul2(*(const __half2*)(qb + gid * 1024 + kk * 16 + tig * 2 + 8), sc8);
            __half2 x3 = __hmul2(*(const __half2*)(qb + (gid + 8) * 1024 + kk * 16 + tig * 2 + 8), sc8);
            qf[kk][0] = *(uint32_t*)&x0; qf[kk][1] = *(uint32_t*)&x1;
            qf[kk][2] = *(uint32_t*)&x2; qf[kk][3] = *(uint32_t*)&x3;
        }
    }

    float oa[8][4];
    #pragma unroll
    for (int nt = 0; nt < 8; nt++)
        #pragma unroll
        for (int r = 0; r < 4; r++) oa[nt][r] = 0.f;
    float m_l = -1e30f, m_h = -1e30f, l_l = 0.f, l_h = 0.f;

    auto load_kv = [&](int j, int buf) {
        const __half* kb = k + (long long)(b * 1024 + j * 128) * 1024 + hcol;
        uint32_t kd = sbase + (buf ? KS1 : KS0);
        #pragma unroll
        for (int c = 0; c < 4; c++) {
            int idx = tid + c * 256;
            int row = idx >> 3, part = idx & 7;
            cpasync16(kd + row * 144 + part * 16, kb + (long long)row * 1024 + part * 8);
        }
        const __half* vb = vt + (long long)hcol * 4096 + b * 1024 + j * 128;
        uint32_t vd = sbase + (buf ? VS1 : VS0);
        #pragma unroll
        for (int c = 0; c < 4; c++) {
            int idx = tid + c * 256;
            int row = idx >> 4, part = idx & 15;
            cpasync16(vd + row * 272 + part * 16, vb + (long long)row * 4096 + part * 8);
        }
    };

    load_kv(0, 0);
    cp_commit();

    for (int j = 0; j <= qi; j++) {
        const int buf = j & 1;
        __syncthreads();
        if (j < qi) load_kv(j + 1, buf ^ 1);
        cp_commit();
        asm volatile("cp.async.wait_group 1;" ::: "memory");
        __syncthreads();

        const uint32_t Ks = sbase + (buf ? KS1 : KS0) + kOffB;
        const uint32_t Vs = sbase + (buf ? VS1 : VS0) + vOffB;
        char* Psm = sm + PS;

        // S = (Q/8) K^T : warp computes 16 x 128
        float sa[16][4];
        #pragma unroll
        for (int nt = 0; nt < 16; nt++)
            #pragma unroll
            for (int r = 0; r < 4; r++) sa[nt][r] = 0.f;
        #pragma unroll
        for (int kk = 0; kk < 4; kk++) {
            #pragma unroll
            for (int p = 0; p < 8; p++) {
                uint32_t bf[4];
                ldsm_x4(bf[0], bf[1], bf[2], bf[3], Ks + p * (16 * 144) + kk * 32);
                mma_f16(sa[2 * p],     qf[kk], bf);
                mma_f16(sa[2 * p + 1], qf[kk], bf + 2);
            }
        }

        if (j == qi) {      // causal mask on diagonal tile
            int rl = w * 16 + gid, rh = rl + 8;
            #pragma unroll
            for (int nt = 0; nt < 16; nt++) {
                int c0 = nt * 8 + tig * 2, c1 = c0 + 1;
                if (c0 > rl) sa[nt][0] = -1e30f;
                if (c1 > rl) sa[nt][1] = -1e30f;
                if (c0 > rh) sa[nt][2] = -1e30f;
                if (c1 > rh) sa[nt][3] = -1e30f;
            }
        }

        // online softmax
        float mxl = -1e30f, mxh = -1e30f;
        #pragma unroll
        for (int nt = 0; nt < 16; nt++) {
            mxl = fmaxf(mxl, fmaxf(sa[nt][0], sa[nt][1]));
            mxh = fmaxf(mxh, fmaxf(sa[nt][2], sa[nt][3]));
        }
        mxl = fmaxf(mxl, __shfl_xor_sync(0xffffffffu, mxl, 1));
        mxl = fmaxf(mxl, __shfl_xor_sync(0xffffffffu, mxl, 2));
        mxh = fmaxf(mxh, __shfl_xor_sync(0xffffffffu, mxh, 1));
        mxh = fmaxf(mxh, __shfl_xor_sync(0xffffffffu, mxh, 2));
        float nml = fmaxf(m_l, mxl), nmh = fmaxf(m_h, mxh);
        float cl = __expf(m_l - nml), ch = __expf(m_h - nmh);
        m_l = nml; m_h = nmh;

        float sl = 0.f, sh = 0.f;
        #pragma unroll
        for (int nt = 0; nt < 16; nt++) {
            float p0 = __expf(sa[nt][0] - m_l);
            float p1 = __expf(sa[nt][1] - m_l);
            float p2 = __expf(sa[nt][2] - m_h);
            float p3 = __expf(sa[nt][3] - m_h);
            sl += p0 + p1; sh += p2 + p3;
            int co = (nt * 8 + tig * 2) * 2;
            *(__half2*)(Psm + (w * 16 + gid) * 272 + co) = __floats2half2_rn(p0, p1);
            *(__half2*)(Psm + (w * 16 + gid + 8) * 272 + co) = __floats2half2_rn(p2, p3);
        }
        sl += __shfl_xor_sync(0xffffffffu, sl, 1);
        sl += __shfl_xor_sync(0xffffffffu, sl, 2);
        sh += __shfl_xor_sync(0xffffffffu, sh, 1);
        sh += __shfl_xor_sync(0xffffffffu, sh, 2);
        l_l = l_l * cl + sl;
        l_h = l_h * ch + sh;
        #pragma unroll
        for (int nt = 0; nt < 8; nt++) {
            oa[nt][0] *= cl; oa[nt][1] *= cl;
            oa[nt][2] *= ch; oa[nt][3] *= ch;
        }
        __syncwarp();   // P rows are warp-private

        // O += P V^T : kk over 128 keys / 16
        const uint32_t Ps = sbase + PS + pOffA;
        #pragma unroll
        for (int kk = 0; kk < 8; kk++) {
            uint32_t af[4];
            ldsm_x4(af[0], af[1], af[2], af[3], Ps + kk * 32);
            #pragma unroll
            for (int p = 0; p < 4; p++) {
                uint32_t bf[4];
                ldsm_x4(bf[0], bf[1], bf[2], bf[3], Vs + p * (16 * 272) + kk * 32);
                mma_f16(oa[2 * p],     af, bf);
                mma_f16(oa[2 * p + 1], af, bf + 2);
            }
        }
    }

    float il = 1.f / l_l, ih = 1.f / l_h;
    #pragma unroll
    for (int nt = 0; nt < 8; nt++) {
        long long r0 = qtok0 + w * 16 + gid;
        int c0 = hcol + nt * 8 + tig * 2;
        *(__half2*)(og + r0 * 1024 + c0) = __floats2half2_rn(oa[nt][0] * il, oa[nt][1] * il);
        *(__half2*)(og + (r0 + 8) * 1024 + c0) = __floats2half2_rn(oa[nt][2] * ih, oa[nt][3] * ih);
    }
}

// ---------------- transpose fp32 -> fp16 [N,K] ----------------
__global__ void __launch_bounds__(256) transpose_k(
    __half* __restrict__ dst, const float* __restrict__ src,
    int R, int Cc, long long srcBatch, long long dstBatch)
{
    __shared__ float t[32][33];
    src += (long long)blockIdx.z * srcBatch;
    dst += (long long)blockIdx.z * dstBatch;
    int c0 = blockIdx.x * 32, r0 = blockIdx.y * 32;
    int x = threadIdx.x, y = threadIdx.y;
    #pragma unroll
    for (int j = 0; j < 32; j += 8)
        t[y + j][x] = src[(long long)(r0 + y + j) * Cc + c0 + x];
    __syncthreads();
    #pragma unroll
    for (int j = 0; j < 32; j += 8)
        dst[(long long)(c0 + y + j) * R + r0 + x] = __float2half(t[x][y + j]);
}

// ---------------- token width detect ----------------
__global__ void detect64_kernel(const int* __restrict__ x32) {
    __shared__ int red[256];
    int o = 0;
    for (int i = threadIdx.x; i < 2048; i += 256) o |= x32[2 * i + 1];
    red[threadIdx.x] = o; __syncthreads();
    for (int st = 128; st > 0; st >>= 1) {
        if (threadIdx.x < st) red[threadIdx.x] |= red[threadIdx.x + st];
        __syncthreads();
    }
    if (threadIdx.x == 0) g_is64 = (red[0] == 0) ? 1 : 0;
}

// ---------------- embedding (fp32 + fp16 copies) ----------------
__global__ __launch_bounds__(256) void embed_kernel(
    const int* __restrict__ x32, const float* __restrict__ tok,
    const float* __restrict__ pos, float* __restrict__ h, __half* __restrict__ h16)
{
    int t = blockIdx.x;
    long long id = g_is64 ? ((const long long*)x32)[t] : (long long)x32[t];
    int s = t & (SEQ - 1);
    const float* tr = tok + id * DMODEL;
    const float* pr = pos + (long long)s * DMODEL;
    long long base = (long long)t * DMODEL;
    for (int i = threadIdx.x; i < DMODEL; i += 256) {
        float v = tr[i] + pr[i];
        h[base + i] = v;
        h16[base + i] = __float2half(v);
    }
}

// ---------------- residual + LayerNorm (fp32, emits fp16 copy) ----------------
__global__ __launch_bounds__(256) void add_ln(
    float* __restrict__ h, __half* __restrict__ h16, const float* __restrict__ t,
    const float* __restrict__ w, const float* __restrict__ b)
{
    __shared__ float buf[DMODEL];
    __shared__ float red[256];
    long long base = (long long)blockIdx.x * DMODEL;
    int tid = threadIdx.x;

    float s = 0.f;
    for (int i = tid; i < DMODEL; i += 256) {
        float x = h[base + i] + t[base + i];
        buf[i] = x; s += x;
    }
    red[tid] = s; __syncthreads();
    for (int st = 128; st > 0; st >>= 1) {
        if (tid < st) red[tid] += red[tid + st];
        __syncthreads();
    }
    float mean = red[0] * (1.f / DMODEL); __syncthreads();

    float s2 = 0.f;
    for (int i = tid; i < DMODEL; i += 256) { float d = buf[i] - mean; s2 += d * d; }
    red[tid] = s2; __syncthreads();
    for (int st = 128; st > 0; st >>= 1) {
        if (tid < st) red[tid] += red[tid + st];
        __syncthreads();
    }
    float inv = rsqrtf(red[0] * (1.f / DMODEL) + 1e-5f);
    for (int i = tid; i < DMODEL; i += 256) {
        float v = (buf[i] - mean) * inv * w[i] + b[i];
        h[base + i] = v;
        h16[base + i] = __float2half(v);
    }
}

__global__ __launch_bounds__(256) void copy_kernel(float* __restrict__ dst,
                                                   const float* __restrict__ src)
{
    long long i = ((long long)blockIdx.x * 256 + threadIdx.x) * 4;
    *(float4*)(dst + i) = *(const float4*)(src + i);
}

// ---------------- host side ----------------
#define GEMM_SMEM (3 * (256 * 144 + 128 * 144))   // 165888
#define FA_SMEM   106496

static void gemm(int chalf,
                 const __half* A, long long aO, long long aI, int lda,
                 const __half* B, long long bO, long long bI, int ldb,
                 void* C, long long cO, long long cI, int ldc,
                 const float* bias, long long biasO, long long biasI, int biasRow,
                 int M, int N, int K, float alpha, int bdiv, int batches, int gelu)
{
    dim3 g(N / 128, M / 256, batches);
    if (chalf)
        gemm_h<1><<<g, 256, GEMM_SMEM>>>(A, aO, aI, lda, B, bO, bI, ldb, C, cO, cI, ldc,
                                         bias, biasO, biasI, biasRow, K, alpha, bdiv, gelu);
    else
        gemm_h<0><<<g, 256, GEMM_SMEM>>>(A, aO, aI, lda, B, bO, bI, ldb, C, cO, cI, ldc,
                                         bias, biasO, biasI, biasRow, K, alpha, bdiv, gelu);
}

extern "C" void kernel_launch(void* const* d_in, const int* in_sizes, int n_in,
                              void* d_out, int out_size)
{
    const int*   x32     = (const int*)  d_in[0];
    const float* tok_emb = (const float*)d_in[1];
    const float* pos_emb = (const float*)d_in[2];
    const float* Wq      = (const float*)d_in[3];
    const float* bq      = (const float*)d_in[4];
    const float* Wk      = (const float*)d_in[5];
    const float* bk      = (const float*)d_in[6];
    const float* Wv      = (const float*)d_in[7];
    const float* bv      = (const float*)d_in[8];
    const float* Wo      = (const float*)d_in[9];
    const float* bo      = (const float*)d_in[10];
    const float* ln1w    = (const float*)d_in[11];
    const float* ln1b    = (const float*)d_in[12];
    const float* ln2w    = (const float*)d_in[13];
    const float* ln2b    = (const float*)d_in[14];
    const float* W1      = (const float*)d_in[15];
    const float* b1      = (const float*)d_in[16];
    const float* W2      = (const float*)d_in[17];
    const float* b2      = (const float*)d_in[18];
    const float* Wout    = (const float*)d_in[19];
    const float* bout    = (const float*)d_in[20];
    float* out = (float*)d_out;

    float *h, *tmp;
    __half *h16, *q16, *k16, *vt16, *o16, *f116;
    __half *wtq, *wtk, *wtv, *wto, *wt1, *wt2, *wtout;
    cudaGetSymbolAddress((void**)&h,    g_h);
    cudaGetSymbolAddress((void**)&h16,  g_h16);
    cudaGetSymbolAddress((void**)&q16,  g_q16);
    cudaGetSymbolAddress((void**)&k16,  g_k16);
    cudaGetSymbolAddress((void**)&vt16, g_vt16);
    cudaGetSymbolAddress((void**)&o16,  g_o16);
    cudaGetSymbolAddress((void**)&tmp,  g_tmp);
    cudaGetSymbolAddress((void**)&f116, g_f116);
    cudaGetSymbolAddress((void**)&wtq,  g_wtq);
    cudaGetSymbolAddress((void**)&wtk,  g_wtk);
    cudaGetSymbolAddress((void**)&wtv,  g_wtv);
    cudaGetSymbolAddress((void**)&wto,  g_wto);
    cudaGetSymbolAddress((void**)&wt1,  g_wt1);
    cudaGetSymbolAddress((void**)&wt2,  g_wt2);
    cudaGetSymbolAddress((void**)&wtout, g_wtout);

    cudaFuncSetAttribute(gemm_h<0>, cudaFuncAttributeMaxDynamicSharedMemorySize, GEMM_SMEM);
    cudaFuncSetAttribute(gemm_h<1>, cudaFuncAttributeMaxDynamicSharedMemorySize, GEMM_SMEM);
    cudaFuncSetAttribute(flash_attn, cudaFuncAttributeMaxDynamicSharedMemorySize, FA_SMEM);

    detect64_kernel<<<1, 256>>>(x32);
    embed_kernel<<<NTOK, 256>>>(x32, tok_emb, pos_emb, h, h16);

    transpose_k<<<dim3(VOCAB / 32, DMODEL / 32, 1), dim3(32, 8)>>>(
        wtout, Wout, DMODEL, VOCAB, 0, 0);

    const long long WQKV_L = (long long)NHEAD * DMODEL * HDIM;
    const long long BQKV_L = (long long)NHEAD * HDIM;
    const long long WO_L   = (long long)DMODEL * DMODEL;
    const long long W1_L   = (long long)DMODEL * FFDIM;
    const long long W2_L   = (long long)FFDIM * DMODEL;

    for (int l = 0; l < NLAYER; l++) {
        const float* bq_l = bq + l * BQKV_L;
        const float* bk_l = bk + l * BQKV_L;
        const float* bv_l = bv + l * BQKV_L;
        const float* bo_l = bo + l * DMODEL;
        const float* b1_l = b1 + l * FFDIM;
        const float* b2_l = b2 + l * DMODEL;

        transpose_k<<<dim3(2, 32, 16), dim3(32, 8)>>>(wtq, Wq + l * WQKV_L,
            DMODEL, HDIM, (long long)DMODEL * HDIM, (long long)HDIM * DMODEL);
        transpose_k<<<dim3(2, 32, 16), dim3(32, 8)>>>(wtk, Wk + l * WQKV_L,
            DMODEL, HDIM, (long long)DMODEL * HDIM, (long long)HDIM * DMODEL);
        transpose_k<<<dim3(2, 32, 16), dim3(32, 8)>>>(wtv, Wv + l * WQKV_L,
            DMODEL, HDIM, (long long)DMODEL * HDIM, (long long)HDIM * DMODEL);
        transpose_k<<<dim3(32, 32, 1), dim3(32, 8)>>>(wto, Wo + l * WO_L,
            DMODEL, DMODEL, 0, 0);
        transpose_k<<<dim3(FFDIM / 32, DMODEL / 32, 1), dim3(32, 8)>>>(wt1, W1 + l * W1_L,
            DMODEL, FFDIM, 0, 0);
        transpose_k<<<dim3(DMODEL / 32, FFDIM / 32, 1), dim3(32, 8)>>>(wt2, W2 + l * W2_L,
            FFDIM, DMODEL, 0, 0);

        // q = h @ Wq + bq ; k = h @ Wk + bk  (fp16 out)
        gemm(1, h16, 0, 0, DMODEL, wtq, 0, 0, DMODEL, q16, 0, 0, DMODEL,
             bq_l, 0, 0, 0, NTOK, DMODEL, DMODEL, 1.f, 1, 1, 0);
        gemm(1, h16, 0, 0, DMODEL, wtk, 0, 0, DMODEL, k16, 0, 0, DMODEL,
             bk_l, 0, 0, 0, NTOK, DMODEL, DMODEL, 1.f, 1, 1, 0);
        // v_t = WvT @ h^T (+ bv per row), fp16 out
        gemm(1, wtv, 0, 0, DMODEL, h16, 0, 0, DMODEL, vt16, 0, 0, NTOK,
             bv_l, 0, 0, 1, DMODEL, NTOK, DMODEL, 1.f, 1, 1, 0);

        flash_attn<<<dim3(8, 64), 256, FA_SMEM>>>(q16, k16, vt16, o16);

        // attn projection -> fp32 tmp
        gemm(0, o16, 0, 0, DMODEL, wto, 0, 0, DMODEL, tmp, 0, 0, DMODEL,
             bo_l, 0, 0, 0, NTOK, DMODEL, DMODEL, 1.f, 1, 1, 0);

        add_ln<<<NTOK, 256>>>(h, h16, tmp, ln1w + l * DMODEL, ln1b + l * DMODEL);

        // FFN: W1 (gelu fused, fp16 out), W2 (fp32 out)
        gemm(1, h16, 0, 0, DMODEL, wt1, 0, 0, DMODEL, f116, 0, 0, FFDIM,
             b1_l, 0, 0, 0, NTOK, FFDIM, DMODEL, 1.f, 1, 1, 1);
        gemm(0, f116, 0, 0, FFDIM, wt2, 0, 0, FFDIM, tmp, 0, 0, DMODEL,
             b2_l, 0, 0, 0, NTOK, DMODEL, FFDIM, 1.f, 1, 1, 0);

        add_ln<<<NTOK, 256>>>(h, h16, tmp, ln2w + l * DMODEL, ln2b + l * DMODEL);
    }

    // logits (fp32 out)
    gemm(0, h16, 0, 0, DMODEL, wtout, 0, 0, DMODEL, out, 0, 0, VOCAB,
         bout, 0, 0, 0, NTOK, VOCAB, DMODEL, 1.f, 1, 1, 0);

    copy_kernel<<<(NTOK * DMODEL) / 1024, 256>>>(out + (long long)NTOK * VOCAB, h);
}

// round 9
// speedup vs baseline: 7.5891x; 1.0711x over previous
#include <cuda_runtime.h>
#include <cuda_fp16.h>
#include <cstdint>

// GPT_78932908966066 — Round 9: 4-stage single-barrier fp16 GEMM mainloop,
// fused QKV (N=3072) GEMM, V via ldmatrix.trans in flash attention,
// vectorized LN/embed, launch order aligned so ncu captures the QKV GEMM.
// L=2, H=16, D=1024, HD=64, FF=4096, V=32000, S=1024, B=4.

#define NTOK   4096
#define DMODEL 1024
#define NHEAD  16
#define HDIM   64
#define FFDIM  4096
#define VOCAB  32000
#define SEQ    1024
#define NLAYER 2

// ---------------- static scratch ----------------
__device__ float  g_h    [NTOK * DMODEL];
__device__ __half g_h16  [NTOK * DMODEL];
__device__ __half g_qkv16[NTOK * 3 * DMODEL];
__device__ __half g_o16  [NTOK * DMODEL];
__device__ float  g_tmp  [NTOK * DMODEL];
__device__ __half g_f116 [NTOK * FFDIM];
__device__ __half g_wqkv [3 * DMODEL * DMODEL];
__device__ __half g_wto  [DMODEL * DMODEL];
__device__ __half g_wt1  [FFDIM * DMODEL];
__device__ __half g_wt2  [DMODEL * FFDIM];
__device__ __half g_wtout[(size_t)VOCAB * DMODEL];
__device__ float  g_bqkv [NLAYER * 3 * DMODEL];
__device__ int    g_is64;

// ---------------- helpers ----------------
__device__ __forceinline__ uint32_t smem_u32(const void* p) {
    uint32_t a;
    asm("{ .reg .u64 t; cvta.to.shared.u64 t, %1; cvt.u32.u64 %0, t; }" : "=r"(a) : "l"(p));
    return a;
}
__device__ __forceinline__ void cpasync16(uint32_t dst, const void* src) {
    asm volatile("cp.async.cg.shared.global [%0], [%1], 16;" :: "r"(dst), "l"(src) : "memory");
}
__device__ __forceinline__ void cp_commit() {
    asm volatile("cp.async.commit_group;" ::: "memory");
}
__device__ __forceinline__ void mma_f16(float* c, const uint32_t* a, const uint32_t* b) {
    asm volatile(
        "mma.sync.aligned.m16n8k16.row.col.f32.f16.f16.f32 "
        "{%0,%1,%2,%3}, {%4,%5,%6,%7}, {%8,%9}, {%0,%1,%2,%3};"
        : "+f"(c[0]), "+f"(c[1]), "+f"(c[2]), "+f"(c[3])
        : "r"(a[0]), "r"(a[1]), "r"(a[2]), "r"(a[3]), "r"(b[0]), "r"(b[1]));
}
__device__ __forceinline__ void ldsm_x4(uint32_t& r0, uint32_t& r1, uint32_t& r2,
                                        uint32_t& r3, uint32_t addr) {
    asm volatile("ldmatrix.sync.aligned.m8n8.x4.shared.b16 {%0,%1,%2,%3}, [%4];"
                 : "=r"(r0), "=r"(r1), "=r"(r2), "=r"(r3) : "r"(addr));
}
__device__ __forceinline__ void ldsm_x4_t(uint32_t& r0, uint32_t& r1, uint32_t& r2,
                                          uint32_t& r3, uint32_t addr) {
    asm volatile("ldmatrix.sync.aligned.m8n8.x4.trans.shared.b16 {%0,%1,%2,%3}, [%4];"
                 : "=r"(r0), "=r"(r1), "=r"(r2), "=r"(r3) : "r"(addr));
}

// ---------------- fp16 NT GEMM: 256x128 CTA, 8 warps (64x64), 4-stage 1-sync ----
template<int CHALF>
__global__ void __launch_bounds__(256, 1) gemm_h(
    const __half* __restrict__ A, long long aO, long long aI, int lda,
    const __half* __restrict__ B, long long bO, long long bI, int ldb,
    void* __restrict__ Cv, long long cO, long long cI, int ldc,
    const float* __restrict__ bias, long long biasO, long long biasI, int biasRow,
    int K, float alpha, int bdiv, int gelu)
{
    constexpr int ASTG = 256 * 144;
    constexpr int BSTG = 128 * 144;
    constexpr int STG  = ASTG + BSTG;   // 55296 bytes per stage

    extern __shared__ char sm[];
    const int rowBase = blockIdx.y * 256;
    const int colBase = blockIdx.x * 128;

    const int z = blockIdx.z;
    const int zo = z / bdiv, zi = z - zo * bdiv;
    A += zo * aO + zi * aI + (long long)rowBase * lda;
    B += zo * bO + zi * bI + (long long)colBase * ldb;
    if (bias) bias += zo * biasO + zi * biasI;

    const int tid = threadIdx.x;
    const int wid = tid >> 5, lane = tid & 31;
    const int gid = lane >> 2, tig = lane & 3;
    const int warpM = wid & 3, warpN = wid >> 2;

    const uint32_t smem_b = smem_u32(sm);

    const uint32_t aOff = (uint32_t)(warpM * 64 + (lane & 15)) * 144 + (lane >> 4) * 16;
    const uint32_t bOff = (uint32_t)(warpN * 64 + ((lane >> 4) * 8) + (lane & 7)) * 144
                        + ((lane >> 3) & 1) * 16;

    const int nk = K >> 6;

    auto load_stage = [&](int s, int i) {
        const int k0 = i << 6;
        uint32_t ab = smem_b + (uint32_t)s * STG;
        #pragma unroll
        for (int c = 0; c < 8; c++) {
            int idx = tid + c * 256;
            int row = idx >> 3, part = idx & 7;
            cpasync16(ab + row * 144 + part * 16, A + (long long)row * lda + k0 + part * 8);
        }
        uint32_t bb = smem_b + (uint32_t)s * STG + ASTG;
        #pragma unroll
        for (int c = 0; c < 4; c++) {
            int idx = tid + c * 256;
            int row = idx >> 3, part = idx & 7;
            cpasync16(bb + row * 144 + part * 16, B + (long long)row * ldb + k0 + part * 8);
        }
    };

    float acc[4][8][4];
    #pragma unroll
    for (int mt = 0; mt < 4; mt++)
        #pragma unroll
        for (int nt = 0; nt < 8; nt++)
            #pragma unroll
            for (int r = 0; r < 4; r++) acc[mt][nt][r] = 0.f;

    load_stage(0, 0); cp_commit();
    if (nk > 1) load_stage(1, 1);
    cp_commit();
    if (nk > 2) load_stage(2, 2);
    cp_commit();

    for (int i = 0; i < nk; i++) {
        asm volatile("cp.async.wait_group 2;" ::: "memory");
        __syncthreads();
        // safe: all warps finished mma(i-1) on stage (i+3)&3 before this write
        if (i + 3 < nk) load_stage((i + 3) & 3, i + 3);
        cp_commit();

        const uint32_t aS = smem_b + (uint32_t)(i & 3) * STG + aOff;
        const uint32_t bS = smem_b + (uint32_t)(i & 3) * STG + ASTG + bOff;
        #pragma unroll
        for (int kk = 0; kk < 4; kk++) {
            uint32_t af[4][4], bf[8][2];
            #pragma unroll
            for (int mt = 0; mt < 4; mt++)
                ldsm_x4(af[mt][0], af[mt][1], af[mt][2], af[mt][3],
                        aS + mt * (16 * 144) + kk * 32);
            #pragma unroll
            for (int p = 0; p < 4; p++)
                ldsm_x4(bf[2 * p][0], bf[2 * p][1], bf[2 * p + 1][0], bf[2 * p + 1][1],
                        bS + p * (16 * 144) + kk * 32);
            #pragma unroll
            for (int mt = 0; mt < 4; mt++)
                #pragma unroll
                for (int nt = 0; nt < 8; nt++)
                    mma_f16(acc[mt][nt], af[mt], bf[nt]);
        }
    }

    #pragma unroll
    for (int mt = 0; mt < 4; mt++) {
        #pragma unroll
        for (int nt = 0; nt < 8; nt++) {
            int row0 = rowBase + warpM * 64 + mt * 16 + gid;
            int col0 = colBase + warpN * 64 + nt * 8 + tig * 2;
            float b0 = 0.f, b1 = 0.f;
            if (bias && !biasRow) { b0 = bias[col0]; b1 = bias[col0 + 1]; }
            #pragma unroll
            for (int hh = 0; hh < 2; hh++) {
                int row = row0 + hh * 8;
                float rb = (bias && biasRow) ? bias[row] : 0.f;
                float v0 = alpha * acc[mt][nt][hh * 2 + 0] + b0 + rb;
                float v1 = alpha * acc[mt][nt][hh * 2 + 1] + b1 + rb;
                if (gelu) {
                    v0 = 0.5f * v0 * (1.f + erff(v0 * 0.70710678118654752f));
                    v1 = 0.5f * v1 * (1.f + erff(v1 * 0.70710678118654752f));
                }
                if (CHALF) {
                    __half2* C = (__half2*)((__half*)Cv + zo * cO + zi * cI);
                    C[((long long)row * ldc + col0) >> 1] = __floats2half2_rn(v0, v1);
                } else {
                    float* C = (float*)Cv + zo * cO + zi * cI;
                    *(float2*)(C + (long long)row * ldc + col0) = make_float2(v0, v1);
                }
            }
        }
    }
}

// ---------------- fused flash attention (reads packed qkv, ld=3072) ----------
// grid (8 q-tiles, 64 z=b*16+h), 256 threads. V consumed untransposed via
// ldmatrix.x4.trans B-fragments.
__global__ void __launch_bounds__(256, 1) flash_attn(
    const __half* __restrict__ qkv, __half* __restrict__ og)
{
    extern __shared__ char sm[];
    // K 2x(128*144)=36864, V 2x(128*144)=36864, P 128*272=34816 -> 108544
    constexpr int KS0 = 0, KS1 = 18432, VS0 = 36864, VS1 = 55296, PS = 73728;
    constexpr int LD = 3 * DMODEL;

    const int qi = blockIdx.x;
    const int z  = blockIdx.y;
    const int b  = z >> 4, hh = z & 15;
    const int hcol = hh * 64;
    const int qtok0 = b * 1024 + qi * 128;

    const int tid = threadIdx.x;
    const int w = tid >> 5, lane = tid & 31;
    const int gid = lane >> 2, tig = lane & 3;

    const uint32_t sbase = smem_u32(sm);

    const uint32_t kOffB = (uint32_t)(((lane >> 4) * 8) + (lane & 7)) * 144
                         + ((lane >> 3) & 1) * 16;                       // K, B-frag
    const uint32_t vOffT = (uint32_t)(((lane >> 3) & 1) * 8 + (lane & 7)) * 144
                         + (lane >> 4) * 16;                             // V, B-frag .trans
    const uint32_t pOffA = (uint32_t)(w * 16 + (lane & 15)) * 272 + (lane >> 4) * 16;

    // Q fragments (scaled by 1/8), register resident
    uint32_t qf[4][4];
    {
        const __half2 sc8 = __floats2half2_rn(0.125f, 0.125f);
        const __half* qb = qkv + (long long)(qtok0 + w * 16) * LD + hcol;
        #pragma unroll
        for (int kk = 0; kk < 4; kk++) {
            __half2 x0 = __hmul2(*(const __half2*)(qb + gid * LD + kk * 16 + tig * 2), sc8);
            __half2 x1 = __hmul2(*(const __half2*)(qb + (gid + 8) * LD + kk * 16 + tig * 2), sc8);
            __half2 x2 = __hmul2(*(const __half2*)(qb + gid * LD + kk * 16 + tig * 2 + 8), sc8);
            __half2 x3 = __hmul2(*(const __half2*)(qb + (gid + 8) * LD + kk * 16 + tig * 2 + 8), sc8);
            qf[kk][0] = *(uint32_t*)&x0; qf[kk][1] = *(uint32_t*)&x1;
            qf[kk][2] = *(uint32_t*)&x2; qf[kk][3] = *(uint32_t*)&x3;
        }
    }

    float oa[8][4];
    #pragma unroll
    for (int nt = 0; nt < 8; nt++)
        #pragma unroll
        for (int r = 0; r < 4; r++) oa[nt][r] = 0.f;
    float m_l = -1e30f, m_h = -1e30f, l_l = 0.f, l_h = 0.f;

    auto load_kv = [&](int j, int buf) {
        const __half* kb = qkv + (long long)(b * 1024 + j * 128) * LD + DMODEL + hcol;
        uint32_t kd = sbase + (buf ? KS1 : KS0);
        #pragma unroll
        for (int c = 0; c < 4; c++) {
            int idx = tid + c * 256;
            int row = idx >> 3, part = idx & 7;
            cpasync16(kd + row * 144 + part * 16, kb + (long long)row * LD + part * 8);
        }
        const __half* vb = qkv + (long long)(b * 1024 + j * 128) * LD + 2 * DMODEL + hcol;
        uint32_t vd = sbase + (buf ? VS1 : VS0);
        #pragma unroll
        for (int c = 0; c < 4; c++) {
            int idx = tid + c * 256;
            int row = idx >> 3, part = idx & 7;
            cpasync16(vd + row * 144 + part * 16, vb + (long long)row * LD + part * 8);
        }
    };

    load_kv(0, 0);
    cp_commit();

    for (int j = 0; j <= qi; j++) {
        const int buf = j & 1;
        __syncthreads();
        if (j < qi) load_kv(j + 1, buf ^ 1);
        cp_commit();
        asm volatile("cp.async.wait_group 1;" ::: "memory");
        __syncthreads();

        const uint32_t Ks = sbase + (buf ? KS1 : KS0) + kOffB;
        const uint32_t Vs = sbase + (buf ? VS1 : VS0) + vOffT;
        char* Psm = sm + PS;

        // S = (Q/8) K^T
        float sa[16][4];
        #pragma unroll
        for (int nt = 0; nt < 16; nt++)
            #pragma unroll
            for (int r = 0; r < 4; r++) sa[nt][r] = 0.f;
        #pragma unroll
        for (int kk = 0; kk < 4; kk++) {
            #pragma unroll
            for (int p = 0; p < 8; p++) {
                uint32_t bf[4];
                ldsm_x4(bf[0], bf[1], bf[2], bf[3], Ks + p * (16 * 144) + kk * 32);
                mma_f16(sa[2 * p],     qf[kk], bf);
                mma_f16(sa[2 * p + 1], qf[kk], bf + 2);
            }
        }

        if (j == qi) {
            int rl = w * 16 + gid, rh = rl + 8;
            #pragma unroll
            for (int nt = 0; nt < 16; nt++) {
                int c0 = nt * 8 + tig * 2, c1 = c0 + 1;
                if (c0 > rl) sa[nt][0] = -1e30f;
                if (c1 > rl) sa[nt][1] = -1e30f;
                if (c0 > rh) sa[nt][2] = -1e30f;
                if (c1 > rh) sa[nt][3] = -1e30f;
            }
        }

        float mxl = -1e30f, mxh = -1e30f;
        #pragma unroll
        for (int nt = 0; nt < 16; nt++) {
            mxl = fmaxf(mxl, fmaxf(sa[nt][0], sa[nt][1]));
            mxh = fmaxf(mxh, fmaxf(sa[nt][2], sa[nt][3]));
        }
        mxl = fmaxf(mxl, __shfl_xor_sync(0xffffffffu, mxl, 1));
        mxl = fmaxf(mxl, __shfl_xor_sync(0xffffffffu, mxl, 2));
        mxh = fmaxf(mxh, __shfl_xor_sync(0xffffffffu, mxh, 1));
        mxh = fmaxf(mxh, __shfl_xor_sync(0xffffffffu, mxh, 2));
        float nml = fmaxf(m_l, mxl), nmh = fmaxf(m_h, mxh);
        float cl = __expf(m_l - nml), ch = __expf(m_h - nmh);
        m_l = nml; m_h = nmh;

        float sl = 0.f, sh = 0.f;
        #pragma unroll
        for (int nt = 0; nt < 16; nt++) {
            float p0 = __expf(sa[nt][0] - m_l);
            float p1 = __expf(sa[nt][1] - m_l);
            float p2 = __expf(sa[nt][2] - m_h);
            float p3 = __expf(sa[nt][3] - m_h);
            sl += p0 + p1; sh += p2 + p3;
            int co = (nt * 8 + tig * 2) * 2;
            *(__half2*)(Psm + (w * 16 + gid) * 272 + co) = __floats2half2_rn(p0, p1);
            *(__half2*)(Psm + (w * 16 + gid + 8) * 272 + co) = __floats2half2_rn(p2, p3);
        }
        sl += __shfl_xor_sync(0xffffffffu, sl, 1);
        sl += __shfl_xor_sync(0xffffffffu, sl, 2);
        sh += __shfl_xor_sync(0xffffffffu, sh, 1);
        sh += __shfl_xor_sync(0xffffffffu, sh, 2);
        l_l = l_l * cl + sl;
        l_h = l_h * ch + sh;
        #pragma unroll
        for (int nt = 0; nt < 8; nt++) {
            oa[nt][0] *= cl; oa[nt][1] *= cl;
            oa[nt][2] *= ch; oa[nt][3] *= ch;
        }
        __syncwarp();

        // O += P V : V rows = tokens, B-frags via ldmatrix.trans
        const uint32_t Ps = sbase + PS + pOffA;
        #pragma unroll
        for (int kk = 0; kk < 8; kk++) {
            uint32_t af[4];
            ldsm_x4(af[0], af[1], af[2], af[3], Ps + kk * 32);
            #pragma unroll
            for (int p = 0; p < 4; p++) {
                uint32_t bf[4];
                ldsm_x4_t(bf[0], bf[1], bf[2], bf[3], Vs + kk * (16 * 144) + p * 32);
                mma_f16(oa[2 * p],     af, bf);
                mma_f16(oa[2 * p + 1], af, bf + 2);
            }
        }
    }

    float il = 1.f / l_l, ih = 1.f / l_h;
    #pragma unroll
    for (int nt = 0; nt < 8; nt++) {
        long long r0 = qtok0 + w * 16 + gid;
        int c0 = hcol + nt * 8 + tig * 2;
        *(__half2*)(og + r0 * 1024 + c0) = __floats2half2_rn(oa[nt][0] * il, oa[nt][1] * il);
        *(__half2*)(og + (r0 + 8) * 1024 + c0) = __floats2half2_rn(oa[nt][2] * ih, oa[nt][3] * ih);
    }
}

// ---------------- transpose fp32 -> fp16 [N,K] ----------------
__global__ void __launch_bounds__(256) transpose_k(
    __half* __restrict__ dst, const float* __restrict__ src,
    int R, int Cc, long long srcBatch, long long dstBatch)
{
    __shared__ float t[32][33];
    src += (long long)blockIdx.z * srcBatch;
    dst += (long long)blockIdx.z * dstBatch;
    int c0 = blockIdx.x * 32, r0 = blockIdx.y * 32;
    int x = threadIdx.x, y = threadIdx.y;
    #pragma unroll
    for (int j = 0; j < 32; j += 8)
        t[y + j][x] = src[(long long)(r0 + y + j) * Cc + c0 + x];
    __syncthreads();
    #pragma unroll
    for (int j = 0; j < 32; j += 8)
        dst[(long long)(c0 + y + j) * R + r0 + x] = __float2half(t[x][y + j]);
}

// ---------------- prep: token-width detect + bias concat ----------------
__global__ void prep_kernel(const int* __restrict__ x32,
                            const float* __restrict__ bq, const float* __restrict__ bk,
                            const float* __restrict__ bv, float* __restrict__ bqkv)
{
    if (blockIdx.x == 0) {
        __shared__ int red[256];
        int o = 0;
        for (int i = threadIdx.x; i < 2048; i += 256) o |= x32[2 * i + 1];
        red[threadIdx.x] = o; __syncthreads();
        for (int st = 128; st > 0; st >>= 1) {
            if (threadIdx.x < st) red[threadIdx.x] |= red[threadIdx.x + st];
            __syncthreads();
        }
        if (threadIdx.x == 0) g_is64 = (red[0] == 0) ? 1 : 0;
    } else {
        int id = blockIdx.x - 1;           // 0..5
        int l = id / 3, wsel = id % 3;
        const float* src = (wsel == 0 ? bq : (wsel == 1 ? bk : bv)) + l * DMODEL;
        float* dst = bqkv + l * 3 * DMODEL + wsel * DMODEL;
        for (int i = threadIdx.x; i < DMODEL; i += 256) dst[i] = src[i];
    }
}

// ---------------- embedding (fp32 + fp16, float4) ----------------
__global__ __launch_bounds__(256) void embed_kernel(
    const int* __restrict__ x32, const float* __restrict__ tok,
    const float* __restrict__ pos, float* __restrict__ h, __half* __restrict__ h16)
{
    int t = blockIdx.x;
    long long id = g_is64 ? ((const long long*)x32)[t] : (long long)x32[t];
    int s = t & (SEQ - 1);
    int i0 = threadIdx.x * 4;
    float4 a = *(const float4*)(tok + id * DMODEL + i0);
    float4 p = *(const float4*)(pos + (long long)s * DMODEL + i0);
    long long base = (long long)t * DMODEL + i0;
    float4 v = make_float4(a.x + p.x, a.y + p.y, a.z + p.z, a.w + p.w);
    *(float4*)(h + base) = v;
    ((__half2*)(h16 + base))[0] = __floats2half2_rn(v.x, v.y);
    ((__half2*)(h16 + base))[1] = __floats2half2_rn(v.z, v.w);
}

// ---------------- residual + LayerNorm (float4, 2 reductions) ----------------
__global__ __launch_bounds__(256) void add_ln(
    const float* __restrict__ hin, float* __restrict__ hout, __half* __restrict__ h16,
    const float* __restrict__ t, const float* __restrict__ w, const float* __restrict__ b)
{
    __shared__ float red[8];
    long long base = (long long)blockIdx.x * DMODEL;
    int tid = threadIdx.x;
    int i0 = tid * 4;

    float4 a = *(const float4*)(hin + base + i0);
    float4 r = *(const float4*)(t + base + i0);
    float x0 = a.x + r.x, x1 = a.y + r.y, x2 = a.z + r.z, x3 = a.w + r.w;

    float s = x0 + x1 + x2 + x3;
    #pragma unroll
    for (int o = 16; o > 0; o >>= 1) s += __shfl_xor_sync(0xffffffffu, s, o);
    if ((tid & 31) == 0) red[tid >> 5] = s;
    __syncthreads();
    float S = red[0] + red[1] + red[2] + red[3] + red[4] + red[5] + red[6] + red[7];
    float mean = S * (1.f / DMODEL);
    __syncthreads();

    float d0 = x0 - mean, d1 = x1 - mean, d2 = x2 - mean, d3 = x3 - mean;
    float s2 = d0 * d0 + d1 * d1 + d2 * d2 + d3 * d3;
    #pragma unroll
    for (int o = 16; o > 0; o >>= 1) s2 += __shfl_xor_sync(0xffffffffu, s2, o);
    if ((tid & 31) == 0) red[tid >> 5] = s2;
    __syncthreads();
    float S2 = red[0] + red[1] + red[2] + red[3] + red[4] + red[5] + red[6] + red[7];
    float inv = rsqrtf(S2 * (1.f / DMODEL) + 1e-5f);

    float4 wv = *(const float4*)(w + i0);
    float4 bv = *(const float4*)(b + i0);
    float y0 = d0 * inv * wv.x + bv.x;
    float y1 = d1 * inv * wv.y + bv.y;
    float y2 = d2 * inv * wv.z + bv.z;
    float y3 = d3 * inv * wv.w + bv.w;
    *(float4*)(hout + base + i0) = make_float4(y0, y1, y2, y3);
    ((__half2*)(h16 + base + i0))[0] = __floats2half2_rn(y0, y1);
    ((__half2*)(h16 + base + i0))[1] = __floats2half2_rn(y2, y3);
}

// ---------------- host side ----------------
#define GEMM_SMEM (4 * (256 * 144 + 128 * 144))   // 221184
#define FA_SMEM   108544

static void gemm(int chalf,
                 const __half* A, long long aO, long long aI, int lda,
                 const __half* B, long long bO, long long bI, int ldb,
                 void* C, long long cO, long long cI, int ldc,
                 const float* bias, long long biasO, long long biasI, int biasRow,
                 int M, int N, int K, float alpha, int bdiv, int batches, int gelu)
{
    dim3 g(N / 128, M / 256, batches);
    if (chalf)
        gemm_h<1><<<g, 256, GEMM_SMEM>>>(A, aO, aI, lda, B, bO, bI, ldb, C, cO, cI, ldc,
                                         bias, biasO, biasI, biasRow, K, alpha, bdiv, gelu);
    else
        gemm_h<0><<<g, 256, GEMM_SMEM>>>(A, aO, aI, lda, B, bO, bI, ldb, C, cO, cI, ldc,
                                         bias, biasO, biasI, biasRow, K, alpha, bdiv, gelu);
}

extern "C" void kernel_launch(void* const* d_in, const int* in_sizes, int n_in,
                              void* d_out, int out_size)
{
    const int*   x32     = (const int*)  d_in[0];
    const float* tok_emb = (const float*)d_in[1];
    const float* pos_emb = (const float*)d_in[2];
    const float* Wq      = (const float*)d_in[3];
    const float* Wk      = (const float*)d_in[5];
    const float* Wv      = (const float*)d_in[7];
    const float* Wo      = (const float*)d_in[9];
    const float* bo      = (const float*)d_in[10];
    const float* ln1w    = (const float*)d_in[11];
    const float* ln1b    = (const float*)d_in[12];
    const float* ln2w    = (const float*)d_in[13];
    const float* ln2b    = (const float*)d_in[14];
    const float* W1      = (const float*)d_in[15];
    const float* b1      = (const float*)d_in[16];
    const float* W2      = (const float*)d_in[17];
    const float* b2      = (const float*)d_in[18];
    const float* Wout    = (const float*)d_in[19];
    const float* bout    = (const float*)d_in[20];
    const float* bq      = (const float*)d_in[4];
    const float* bk      = (const float*)d_in[6];
    const float* bv      = (const float*)d_in[8];
    float* out = (float*)d_out;

    float *h, *tmp, *bqkv;
    __half *h16, *qkv16, *o16, *f116;
    __half *wqkv, *wto, *wt1, *wt2, *wtout;
    cudaGetSymbolAddress((void**)&h,     g_h);
    cudaGetSymbolAddress((void**)&h16,   g_h16);
    cudaGetSymbolAddress((void**)&qkv16, g_qkv16);
    cudaGetSymbolAddress((void**)&o16,   g_o16);
    cudaGetSymbolAddress((void**)&tmp,   g_tmp);
    cudaGetSymbolAddress((void**)&f116,  g_f116);
    cudaGetSymbolAddress((void**)&wqkv,  g_wqkv);
    cudaGetSymbolAddress((void**)&wto,   g_wto);
    cudaGetSymbolAddress((void**)&wt1,   g_wt1);
    cudaGetSymbolAddress((void**)&wt2,   g_wt2);
    cudaGetSymbolAddress((void**)&wtout, g_wtout);
    cudaGetSymbolAddress((void**)&bqkv,  g_bqkv);

    cudaFuncSetAttribute(gemm_h<0>, cudaFuncAttributeMaxDynamicSharedMemorySize, GEMM_SMEM);
    cudaFuncSetAttribute(gemm_h<1>, cudaFuncAttributeMaxDynamicSharedMemorySize, GEMM_SMEM);
    cudaFuncSetAttribute(flash_attn, cudaFuncAttributeMaxDynamicSharedMemorySize, FA_SMEM);

    const long long WQKV_L = (long long)NHEAD * DMODEL * HDIM;
    const long long WO_L   = (long long)DMODEL * DMODEL;
    const long long W1_L   = (long long)DMODEL * FFDIM;
    const long long W2_L   = (long long)FFDIM * DMODEL;

    // launches 1,2
    prep_kernel<<<7, 256>>>(x32, bq, bk, bv, bqkv);
    embed_kernel<<<NTOK, 256>>>(x32, tok_emb, pos_emb, h, h16);

    for (int l = 0; l < NLAYER; l++) {
        const float* bo_l = bo + l * DMODEL;
        const float* b1_l = b1 + l * FFDIM;
        const float* b2_l = b2 + l * DMODEL;

        // QKV weight transposes into packed [3072,1024] (launches 3,4,5 for l=0)
        transpose_k<<<dim3(2, 32, 16), dim3(32, 8)>>>(wqkv, Wq + l * WQKV_L,
            DMODEL, HDIM, (long long)DMODEL * HDIM, (long long)HDIM * DMODEL);
        transpose_k<<<dim3(2, 32, 16), dim3(32, 8)>>>(wqkv + DMODEL * DMODEL, Wk + l * WQKV_L,
            DMODEL, HDIM, (long long)DMODEL * HDIM, (long long)HDIM * DMODEL);
        transpose_k<<<dim3(2, 32, 16), dim3(32, 8)>>>(wqkv + 2 * DMODEL * DMODEL, Wv + l * WQKV_L,
            DMODEL, HDIM, (long long)DMODEL * HDIM, (long long)HDIM * DMODEL);

        // fused QKV GEMM (launch 6 for l=0 -> ncu -s 5 -c 1 captures this)
        gemm(1, h16, 0, 0, DMODEL, wqkv, 0, 0, DMODEL, qkv16, 0, 0, 3 * DMODEL,
             bqkv + l * 3 * DMODEL, 0, 0, 0, NTOK, 3 * DMODEL, DMODEL, 1.f, 1, 1, 0);

        transpose_k<<<dim3(32, 32, 1), dim3(32, 8)>>>(wto, Wo + l * WO_L,
            DMODEL, DMODEL, 0, 0);
        transpose_k<<<dim3(FFDIM / 32, DMODEL / 32, 1), dim3(32, 8)>>>(wt1, W1 + l * W1_L,
            DMODEL, FFDIM, 0, 0);
        transpose_k<<<dim3(DMODEL / 32, FFDIM / 32, 1), dim3(32, 8)>>>(wt2, W2 + l * W2_L,
            FFDIM, DMODEL, 0, 0);

        flash_attn<<<dim3(8, 64), 256, FA_SMEM>>>(qkv16, o16);

        gemm(0, o16, 0, 0, DMODEL, wto, 0, 0, DMODEL, tmp, 0, 0, DMODEL,
             bo_l, 0, 0, 0, NTOK, DMODEL, DMODEL, 1.f, 1, 1, 0);

        add_ln<<<NTOK, 256>>>(h, h, h16, tmp, ln1w + l * DMODEL, ln1b + l * DMODEL);

        gemm(1, h16, 0, 0, DMODEL, wt1, 0, 0, DMODEL, f116, 0, 0, FFDIM,
             b1_l, 0, 0, 0, NTOK, FFDIM, DMODEL, 1.f, 1, 1, 1);
        gemm(0, f116, 0, 0, FFDIM, wt2, 0, 0, FFDIM, tmp, 0, 0, DMODEL,
             b2_l, 0, 0, 0, NTOK, DMODEL, FFDIM, 1.f, 1, 1, 0);

        // last LN writes fp32 result straight into the output tail
        float* lnout = (l == NLAYER - 1) ? (out + (long long)NTOK * VOCAB) : h;
        add_ln<<<NTOK, 256>>>(h, lnout, h16, tmp, ln2w + l * DMODEL, ln2b + l * DMODEL);
    }

    transpose_k<<<dim3(VOCAB / 32, DMODEL / 32, 1), dim3(32, 8)>>>(
        wtout, Wout, DMODEL, VOCAB, 0, 0);
    gemm(0, h16, 0, 0, DMODEL, wtout, 0, 0, DMODEL, out, 0, 0, VOCAB,
         bout, 0, 0, 0, NTOK, VOCAB, DMODEL, 1.f, 1, 1, 0);
}